// round 1
// baseline (speedup 1.0000x reference)
#include <cuda_runtime.h>
#include <cstdint>

#define BATCH 8
#define NQ 1024
#define NK 1024
#define DMODEL 512
#define NHEAD 8
#define DHEAD 64
#define MROWS (BATCH * NQ)   // 8192

// ---------------- scratch (no allocation allowed) ----------------
__device__ float g_Qp[(size_t)MROWS * DMODEL];
__device__ float g_Kp[(size_t)MROWS * DMODEL];
__device__ float g_Vp[(size_t)MROWS * DMODEL];
__device__ float g_O [(size_t)MROWS * DMODEL];

// ---------------- GEMM: C[M,512] = A[M,512] @ W[512,512] + b ----------------
// FUSE=1: C = A + relu(A@W + b)   (MLP branch, residual on same A)
template <int FUSE>
__global__ __launch_bounds__(256) void gemm512(
    const float* __restrict__ A, const float* __restrict__ W,
    const float* __restrict__ bias, float* __restrict__ C)
{
    __shared__ float As[16][68];   // [k][m], padded
    __shared__ float Ws[16][64];   // [k][n]

    const int n0 = blockIdx.x * 64;
    const int m0 = blockIdx.y * 64;
    const int tid = threadIdx.x;
    const int tx = tid & 15;       // n quad
    const int ty = tid >> 4;       // m quad

    const int lrow = tid >> 2, lc4 = tid & 3;   // A tile load: 64 rows x 4 float4
    const int wr = tid >> 4, wc = tid & 15;     // W tile load: 16 rows x 16 float4

    float acc[4][4];
    #pragma unroll
    for (int i = 0; i < 4; i++)
        #pragma unroll
        for (int j = 0; j < 4; j++) acc[i][j] = 0.f;

    for (int k0 = 0; k0 < 512; k0 += 16) {
        float4 a = *(const float4*)(A + (size_t)(m0 + lrow) * 512 + k0 + lc4 * 4);
        float4 w = *(const float4*)(W + (size_t)(k0 + wr) * 512 + n0 + wc * 4);
        As[lc4 * 4 + 0][lrow] = a.x;
        As[lc4 * 4 + 1][lrow] = a.y;
        As[lc4 * 4 + 2][lrow] = a.z;
        As[lc4 * 4 + 3][lrow] = a.w;
        *(float4*)&Ws[wr][wc * 4] = w;
        __syncthreads();

        #pragma unroll
        for (int k = 0; k < 16; k++) {
            float4 av = *(const float4*)&As[k][ty * 4];
            float4 wv = *(const float4*)&Ws[k][tx * 4];
            acc[0][0] += av.x * wv.x; acc[0][1] += av.x * wv.y;
            acc[0][2] += av.x * wv.z; acc[0][3] += av.x * wv.w;
            acc[1][0] += av.y * wv.x; acc[1][1] += av.y * wv.y;
            acc[1][2] += av.y * wv.z; acc[1][3] += av.y * wv.w;
            acc[2][0] += av.z * wv.x; acc[2][1] += av.z * wv.y;
            acc[2][2] += av.z * wv.z; acc[2][3] += av.z * wv.w;
            acc[3][0] += av.w * wv.x; acc[3][1] += av.w * wv.y;
            acc[3][2] += av.w * wv.z; acc[3][3] += av.w * wv.w;
        }
        __syncthreads();
    }

    const int nn = n0 + tx * 4;
    float4 bb = *(const float4*)(bias + nn);
    #pragma unroll
    for (int i = 0; i < 4; i++) {
        const int mm = m0 + ty * 4 + i;
        float4 o;
        o.x = acc[i][0] + bb.x;
        o.y = acc[i][1] + bb.y;
        o.z = acc[i][2] + bb.z;
        o.w = acc[i][3] + bb.w;
        if (FUSE) {
            float4 xres = *(const float4*)(A + (size_t)mm * 512 + nn);
            o.x = xres.x + fmaxf(o.x, 0.f);
            o.y = xres.y + fmaxf(o.y, 0.f);
            o.z = xres.z + fmaxf(o.z, 0.f);
            o.w = xres.w + fmaxf(o.w, 0.f);
        }
        *(float4*)(C + (size_t)mm * 512 + nn) = o;
    }
}

// ---------------- Attention: per (b, h, q-tile of 64) flash-style ----------------
// Thread layout: r = tid>>2 (q row 0..63), sub = tid&3 (16-wide d/col slice).
// Scores: partial dot over d-slice + 2-step butterfly reduce -> all 4 lanes hold
// the full score row. Online softmax in 32-k chunks. Residual += Qh fused.
__global__ __launch_bounds__(256) void attn_kernel(
    const float* __restrict__ Qp, const float* __restrict__ Kp,
    const float* __restrict__ Vp, float* __restrict__ O)
{
    __shared__ float Ks[64][68];
    __shared__ float Vs[64][68];

    const int qt = blockIdx.x, h = blockIdx.y, b = blockIdx.z;
    const int tid = threadIdx.x;
    const int r = tid >> 2, sub = tid & 3;

    const float* qptr = Qp + ((size_t)(b * NQ + qt * 64 + r)) * DMODEL + h * DHEAD + sub * 16;
    float q[16];   // scaled by 1/sqrt(64)
    #pragma unroll
    for (int i = 0; i < 16; i += 4) {
        float4 v = *(const float4*)(qptr + i);
        q[i + 0] = v.x * 0.125f; q[i + 1] = v.y * 0.125f;
        q[i + 2] = v.z * 0.125f; q[i + 3] = v.w * 0.125f;
    }

    float m = -1e30f, l = 0.f;
    float acc[16];
    #pragma unroll
    for (int i = 0; i < 16; i++) acc[i] = 0.f;

    for (int kt = 0; kt < NK / 64; kt++) {
        __syncthreads();
        #pragma unroll
        for (int i = tid; i < 64 * 16; i += 256) {
            const int row = i >> 4, c4 = i & 15;
            const size_t gk = ((size_t)(b * NK + kt * 64 + row)) * DMODEL + h * DHEAD + c4 * 4;
            *(float4*)&Ks[row][c4 * 4] = *(const float4*)(Kp + gk);
            *(float4*)&Vs[row][c4 * 4] = *(const float4*)(Vp + gk);
        }
        __syncthreads();

        #pragma unroll
        for (int half = 0; half < 2; half++) {
            float s[32];
            #pragma unroll
            for (int k = 0; k < 32; k++) {
                const int kk = half * 32 + k;
                float a0 = 0.f;
                #pragma unroll
                for (int j = 0; j < 16; j += 4) {
                    float4 kv = *(const float4*)&Ks[kk][sub * 16 + j];
                    a0 += q[j] * kv.x + q[j + 1] * kv.y + q[j + 2] * kv.z + q[j + 3] * kv.w;
                }
                s[k] = a0;
            }
            #pragma unroll
            for (int k = 0; k < 32; k++) {
                s[k] += __shfl_xor_sync(0xffffffffu, s[k], 1);
                s[k] += __shfl_xor_sync(0xffffffffu, s[k], 2);
            }
            float cmax = s[0];
            #pragma unroll
            for (int k = 1; k < 32; k++) cmax = fmaxf(cmax, s[k]);
            const float mnew = fmaxf(m, cmax);
            const float corr = __expf(m - mnew);
            l *= corr;
            #pragma unroll
            for (int c = 0; c < 16; c++) acc[c] *= corr;
            float ps = 0.f;
            #pragma unroll
            for (int k = 0; k < 32; k++) {
                const float p = __expf(s[k] - mnew);
                s[k] = p; ps += p;
            }
            l += ps;
            m = mnew;
            #pragma unroll
            for (int k = 0; k < 32; k++) {
                const int kk = half * 32 + k;
                #pragma unroll
                for (int c = 0; c < 16; c += 4) {
                    float4 vv = *(const float4*)&Vs[kk][sub * 16 + c];
                    acc[c + 0] += s[k] * vv.x;
                    acc[c + 1] += s[k] * vv.y;
                    acc[c + 2] += s[k] * vv.z;
                    acc[c + 3] += s[k] * vv.w;
                }
            }
        }
    }

    const float inv = 1.f / l;
    float* optr = O + ((size_t)(b * NQ + qt * 64 + r)) * DMODEL + h * DHEAD + sub * 16;
    #pragma unroll
    for (int c = 0; c < 16; c += 4) {
        float4 o;
        o.x = acc[c + 0] * inv + q[c + 0] * 8.f;   // residual: unscale q
        o.y = acc[c + 1] * inv + q[c + 1] * 8.f;
        o.z = acc[c + 2] * inv + q[c + 2] * 8.f;
        o.w = acc[c + 3] * inv + q[c + 3] * 8.f;
        *(float4*)(optr + c) = o;
    }
}

// ---------------- LayerNorm over last dim (512) ----------------
__global__ __launch_bounds__(128) void ln512(
    const float* __restrict__ X, const float* __restrict__ g,
    const float* __restrict__ be, float* __restrict__ Y)
{
    const int row = blockIdx.x;
    const int tid = threadIdx.x;
    const float* x = X + (size_t)row * 512;

    float4 v = *(const float4*)(x + tid * 4);
    float s  = v.x + v.y + v.z + v.w;
    float ss = v.x * v.x + v.y * v.y + v.z * v.z + v.w * v.w;
    #pragma unroll
    for (int o = 16; o; o >>= 1) {
        s  += __shfl_xor_sync(0xffffffffu, s, o);
        ss += __shfl_xor_sync(0xffffffffu, ss, o);
    }
    __shared__ float sm[4], sm2[4];
    if ((tid & 31) == 0) { sm[tid >> 5] = s; sm2[tid >> 5] = ss; }
    __syncthreads();
    const float ts  = sm[0] + sm[1] + sm[2] + sm[3];
    const float tss = sm2[0] + sm2[1] + sm2[2] + sm2[3];
    const float mean = ts * (1.f / 512.f);
    const float var  = tss * (1.f / 512.f) - mean * mean;
    const float rstd = rsqrtf(var + 1e-5f);

    float4 gg = *(const float4*)(g + tid * 4);
    float4 bb = *(const float4*)(be + tid * 4);
    float4 o;
    o.x = (v.x - mean) * rstd * gg.x + bb.x;
    o.y = (v.y - mean) * rstd * gg.y + bb.y;
    o.z = (v.z - mean) * rstd * gg.z + bb.z;
    o.w = (v.w - mean) * rstd * gg.w + bb.w;
    *(float4*)(Y + (size_t)row * 512 + tid * 4) = o;
}

// ---------------- launch ----------------
extern "C" void kernel_launch(void* const* d_in, const int* in_sizes, int n_in,
                              void* d_out, int out_size)
{
    const float* Q  = (const float*)d_in[0];
    const float* K  = (const float*)d_in[1];
    const float* Wq = (const float*)d_in[2];
    const float* bq = (const float*)d_in[3];
    const float* Wk = (const float*)d_in[4];
    const float* bk = (const float*)d_in[5];
    const float* Wv = (const float*)d_in[6];
    const float* bv = (const float*)d_in[7];
    const float* Wo = (const float*)d_in[8];
    const float* bo = (const float*)d_in[9];
    const float* g0 = (const float*)d_in[10];
    const float* b0 = (const float*)d_in[11];
    const float* g1 = (const float*)d_in[12];
    const float* b1 = (const float*)d_in[13];
    float* out = (float*)d_out;

    float *Qp, *Kp, *Vp, *Obuf;
    cudaGetSymbolAddress((void**)&Qp, g_Qp);
    cudaGetSymbolAddress((void**)&Kp, g_Kp);
    cudaGetSymbolAddress((void**)&Vp, g_Vp);
    cudaGetSymbolAddress((void**)&Obuf, g_O);

    dim3 gg(DMODEL / 64, MROWS / 64);   // (8, 128)

    gemm512<0><<<gg, 256>>>(Q, Wq, bq, Qp);
    gemm512<0><<<gg, 256>>>(K, Wk, bk, Kp);
    gemm512<0><<<gg, 256>>>(K, Wv, bv, Vp);

    attn_kernel<<<dim3(NQ / 64, NHEAD, BATCH), 256>>>(Qp, Kp, Vp, Obuf);

    ln512<<<MROWS, 128>>>(Obuf, g0, b0, Qp);        // X (reuse g_Qp)
    gemm512<1><<<gg, 256>>>(Qp, Wo, bo, Kp);        // Y = X + relu(X@Wo+bo) (reuse g_Kp)
    ln512<<<MROWS, 128>>>(Kp, g1, b1, out);
}

// round 3
// speedup vs baseline: 1.0935x; 1.0935x over previous
#include <cuda_runtime.h>
#include <cuda_bf16.h>
#include <cstdint>

#define BATCH 8
#define NQ 1024
#define NK 1024
#define DMODEL 512
#define NHEAD 8
#define DHEAD 64
#define MROWS (BATCH * NQ)   // 8192
#define AST 40               // smem row stride in bf16 (32 data + 8 pad)

// ---------------- scratch (no allocation allowed) ----------------
__device__ float g_Qp[(size_t)MROWS * DMODEL];
__device__ float g_Kp[(size_t)MROWS * DMODEL];
__device__ float g_Vp[(size_t)MROWS * DMODEL];
__device__ float g_O [(size_t)MROWS * DMODEL];
__device__ __nv_bfloat16 g_Ah[(size_t)MROWS * DMODEL];
__device__ __nv_bfloat16 g_Al[(size_t)MROWS * DMODEL];
__device__ __nv_bfloat16 g_Bh[(size_t)MROWS * DMODEL];
__device__ __nv_bfloat16 g_Bl[(size_t)MROWS * DMODEL];
__device__ __nv_bfloat16 g_Wth[4 * 512 * 512];   // W^T hi: [n][k]
__device__ __nv_bfloat16 g_Wtl[4 * 512 * 512];   // W^T lo: [n][k]

// ---------------- warp-mma helpers (base PTX, sm_80+, works on sm_103) ----------------
__device__ __forceinline__ uint32_t s2u(const void* p) {
    uint32_t a;
    asm("{ .reg .u64 t; cvta.to.shared.u64 t, %1; cvt.u32.u64 %0, t; }" : "=r"(a) : "l"(p));
    return a;
}

__device__ __forceinline__ void ldsm_x4(uint32_t* r, uint32_t addr) {
    asm volatile("ldmatrix.sync.aligned.m8n8.x4.shared.b16 {%0,%1,%2,%3}, [%4];"
                 : "=r"(r[0]), "=r"(r[1]), "=r"(r[2]), "=r"(r[3]) : "r"(addr));
}

__device__ __forceinline__ void mma16816(float* d, const uint32_t* a, const uint32_t* b) {
    asm volatile(
        "mma.sync.aligned.m16n8k16.row.col.f32.bf16.bf16.f32 "
        "{%0,%1,%2,%3}, {%4,%5,%6,%7}, {%8,%9}, {%0,%1,%2,%3};"
        : "+f"(d[0]), "+f"(d[1]), "+f"(d[2]), "+f"(d[3])
        : "r"(a[0]), "r"(a[1]), "r"(a[2]), "r"(a[3]), "r"(b[0]), "r"(b[1]));
}

// ---------------- conversion kernels ----------------
// fp32 -> bf16 hi + bf16 lo (residual)
__global__ __launch_bounds__(256) void conv_act(
    const float* __restrict__ X, __nv_bfloat16* __restrict__ H,
    __nv_bfloat16* __restrict__ L)
{
    const size_t i = (size_t)blockIdx.x * 256 + threadIdx.x;   // float4 index
    float4 v = ((const float4*)X)[i];
    __nv_bfloat16 h0 = __float2bfloat16(v.x), h1 = __float2bfloat16(v.y);
    __nv_bfloat16 h2 = __float2bfloat16(v.z), h3 = __float2bfloat16(v.w);
    __nv_bfloat16 l0 = __float2bfloat16(v.x - __bfloat162float(h0));
    __nv_bfloat16 l1 = __float2bfloat16(v.y - __bfloat162float(h1));
    __nv_bfloat16 l2 = __float2bfloat16(v.z - __bfloat162float(h2));
    __nv_bfloat16 l3 = __float2bfloat16(v.w - __bfloat162float(h3));
    ((__nv_bfloat162*)H)[2 * i + 0] = __nv_bfloat162(h0, h1);
    ((__nv_bfloat162*)H)[2 * i + 1] = __nv_bfloat162(h2, h3);
    ((__nv_bfloat162*)L)[2 * i + 0] = __nv_bfloat162(l0, l1);
    ((__nv_bfloat162*)L)[2 * i + 1] = __nv_bfloat162(l2, l3);
}

// W[512 k][512 n] fp32 -> Wt[512 n][512 k] bf16 hi/lo (transpose + split)
__global__ __launch_bounds__(256) void conv_wt(
    const float* __restrict__ W, __nv_bfloat16* __restrict__ Th,
    __nv_bfloat16* __restrict__ Tl)
{
    __shared__ float t[32][33];
    const int bx = blockIdx.x * 32;  // n
    const int by = blockIdx.y * 32;  // k
    const int x = threadIdx.x, y0 = threadIdx.y;
    #pragma unroll
    for (int j = 0; j < 32; j += 8)
        t[y0 + j][x] = W[(size_t)(by + y0 + j) * 512 + bx + x];   // t[k_local][n_local]
    __syncthreads();
    #pragma unroll
    for (int j = 0; j < 32; j += 8) {
        float v = t[x][y0 + j];   // W[by+x][bx+y0+j]
        __nv_bfloat16 h = __float2bfloat16(v);
        __nv_bfloat16 l = __float2bfloat16(v - __bfloat162float(h));
        const size_t o = (size_t)(bx + y0 + j) * 512 + by + x;
        Th[o] = h;
        Tl[o] = l;
    }
}

// ---------------- warp-mma GEMM: C[M,512] = fp32(A) @ fp32(W) + bias ----------------
// A as bf16 hi/lo [M,512] row-major (k-major); B as W^T bf16 hi/lo [512 n][512 k].
// 3-term split: D = Ah@Bh + Ah@Bl + Al@Bh. fuse!=0: C = resid + relu(D + bias).
// CTA tile 128m x 64n, BK=32. 8 warps: warp_m = wid&3 (32 rows), warp_n = wid>>2 (32 cols).
__global__ __launch_bounds__(256) void tc_gemm(
    const __nv_bfloat16* __restrict__ Ah, const __nv_bfloat16* __restrict__ Al,
    const __nv_bfloat16* __restrict__ Bh, const __nv_bfloat16* __restrict__ Bl,
    const float* __restrict__ bias, const float* __restrict__ resid,
    float* __restrict__ C, int fuse)
{
    __shared__ __nv_bfloat16 sAh[128 * AST];
    __shared__ __nv_bfloat16 sAl[128 * AST];
    __shared__ __nv_bfloat16 sBh[64 * AST];
    __shared__ __nv_bfloat16 sBl[64 * AST];

    const int tid = threadIdx.x, wid = tid >> 5, lane = tid & 31;
    const int m0 = blockIdx.y * 128, n0 = blockIdx.x * 64;
    const int warp_m = (wid & 3) * 32, warp_n = (wid >> 2) * 32;

    float acc[2][4][4];
    #pragma unroll
    for (int mt = 0; mt < 2; mt++)
        #pragma unroll
        for (int nt = 0; nt < 4; nt++)
            #pragma unroll
            for (int i = 0; i < 4; i++) acc[mt][nt][i] = 0.f;

    // ldmatrix lane addressing (precompute offsets in elements)
    const int a_row = lane & 15, a_cb = (lane >> 4) * 8;                 // A x4
    const int b_nof = (lane & 7) + ((lane >> 4) & 1) * 8;               // B x4
    const int b_kof = ((lane >> 3) & 1) * 8;

    for (int kc = 0; kc < 16; kc++) {
        // ---- load chunk: A 128x32 (hi+lo), B 64x32 (hi+lo) ----
        #pragma unroll
        for (int i = 0; i < 2; i++) {
            const int idx = i * 256 + tid;
            const int row = idx >> 2, c = idx & 3;
            const size_t go = (size_t)(m0 + row) * 512 + kc * 32 + c * 8;
            *(uint4*)&sAh[row * AST + c * 8] = *(const uint4*)(Ah + go);
            *(uint4*)&sAl[row * AST + c * 8] = *(const uint4*)(Al + go);
        }
        {
            const int row = tid >> 2, c = tid & 3;
            const size_t go = (size_t)(n0 + row) * 512 + kc * 32 + c * 8;
            *(uint4*)&sBh[row * AST + c * 8] = *(const uint4*)(Bh + go);
            *(uint4*)&sBl[row * AST + c * 8] = *(const uint4*)(Bl + go);
        }
        __syncthreads();

        #pragma unroll
        for (int ks = 0; ks < 2; ks++) {
            const int k16 = ks * 16;
            uint32_t afh[2][4], afl[2][4], bfh[2][4], bfl[2][4];
            #pragma unroll
            for (int mt = 0; mt < 2; mt++) {
                const int off = (warp_m + mt * 16 + a_row) * AST + k16 + a_cb;
                ldsm_x4(afh[mt], s2u(&sAh[off]));
                ldsm_x4(afl[mt], s2u(&sAl[off]));
            }
            #pragma unroll
            for (int nb = 0; nb < 2; nb++) {
                const int off = (warp_n + nb * 16 + b_nof) * AST + k16 + b_kof;
                ldsm_x4(bfh[nb], s2u(&sBh[off]));
                ldsm_x4(bfl[nb], s2u(&sBl[off]));
            }
            #pragma unroll
            for (int mt = 0; mt < 2; mt++)
                #pragma unroll
                for (int nt = 0; nt < 4; nt++) {
                    const uint32_t* bh = &bfh[nt >> 1][(nt & 1) * 2];
                    const uint32_t* bl = &bfl[nt >> 1][(nt & 1) * 2];
                    mma16816(acc[mt][nt], afh[mt], bh);
                    mma16816(acc[mt][nt], afh[mt], bl);
                    mma16816(acc[mt][nt], afl[mt], bh);
                }
        }
        __syncthreads();
    }

    // ---- epilogue ----
    const int r0 = lane >> 2, c0 = (lane & 3) * 2;
    #pragma unroll
    for (int mt = 0; mt < 2; mt++) {
        #pragma unroll
        for (int nt = 0; nt < 4; nt++) {
            const int cc = n0 + warp_n + nt * 8 + c0;
            const float2 bb = *(const float2*)(bias + cc);
            #pragma unroll
            for (int half = 0; half < 2; half++) {
                const int rr = m0 + warp_m + mt * 16 + r0 + half * 8;
                float2 o;
                o.x = acc[mt][nt][half * 2 + 0] + bb.x;
                o.y = acc[mt][nt][half * 2 + 1] + bb.y;
                if (fuse) {
                    float2 xr = *(const float2*)(resid + (size_t)rr * 512 + cc);
                    o.x = xr.x + fmaxf(o.x, 0.f);
                    o.y = xr.y + fmaxf(o.y, 0.f);
                }
                *(float2*)(C + (size_t)rr * 512 + cc) = o;
            }
        }
    }
}

// ---------------- Attention (fp32, unchanged) ----------------
__global__ __launch_bounds__(256) void attn_kernel(
    const float* __restrict__ Qp, const float* __restrict__ Kp,
    const float* __restrict__ Vp, float* __restrict__ O)
{
    __shared__ float Ks[64][68];
    __shared__ float Vs[64][68];

    const int qt = blockIdx.x, h = blockIdx.y, b = blockIdx.z;
    const int tid = threadIdx.x;
    const int r = tid >> 2, sub = tid & 3;

    const float* qptr = Qp + ((size_t)(b * NQ + qt * 64 + r)) * DMODEL + h * DHEAD + sub * 16;
    float q[16];
    #pragma unroll
    for (int i = 0; i < 16; i += 4) {
        float4 v = *(const float4*)(qptr + i);
        q[i + 0] = v.x * 0.125f; q[i + 1] = v.y * 0.125f;
        q[i + 2] = v.z * 0.125f; q[i + 3] = v.w * 0.125f;
    }

    float m = -1e30f, l = 0.f;
    float acc[16];
    #pragma unroll
    for (int i = 0; i < 16; i++) acc[i] = 0.f;

    for (int kt = 0; kt < NK / 64; kt++) {
        __syncthreads();
        #pragma unroll
        for (int i = tid; i < 64 * 16; i += 256) {
            const int row = i >> 4, c4 = i & 15;
            const size_t gk = ((size_t)(b * NK + kt * 64 + row)) * DMODEL + h * DHEAD + c4 * 4;
            *(float4*)&Ks[row][c4 * 4] = *(const float4*)(Kp + gk);
            *(float4*)&Vs[row][c4 * 4] = *(const float4*)(Vp + gk);
        }
        __syncthreads();

        #pragma unroll
        for (int half = 0; half < 2; half++) {
            float s[32];
            #pragma unroll
            for (int k = 0; k < 32; k++) {
                const int kk = half * 32 + k;
                float a0 = 0.f;
                #pragma unroll
                for (int j = 0; j < 16; j += 4) {
                    float4 kv = *(const float4*)&Ks[kk][sub * 16 + j];
                    a0 += q[j] * kv.x + q[j + 1] * kv.y + q[j + 2] * kv.z + q[j + 3] * kv.w;
                }
                s[k] = a0;
            }
            #pragma unroll
            for (int k = 0; k < 32; k++) {
                s[k] += __shfl_xor_sync(0xffffffffu, s[k], 1);
                s[k] += __shfl_xor_sync(0xffffffffu, s[k], 2);
            }
            float cmax = s[0];
            #pragma unroll
            for (int k = 1; k < 32; k++) cmax = fmaxf(cmax, s[k]);
            const float mnew = fmaxf(m, cmax);
            const float corr = __expf(m - mnew);
            l *= corr;
            #pragma unroll
            for (int c = 0; c < 16; c++) acc[c] *= corr;
            float ps = 0.f;
            #pragma unroll
            for (int k = 0; k < 32; k++) {
                const float p = __expf(s[k] - mnew);
                s[k] = p; ps += p;
            }
            l += ps;
            m = mnew;
            #pragma unroll
            for (int k = 0; k < 32; k++) {
                const int kk = half * 32 + k;
                #pragma unroll
                for (int c = 0; c < 16; c += 4) {
                    float4 vv = *(const float4*)&Vs[kk][sub * 16 + c];
                    acc[c + 0] += s[k] * vv.x;
                    acc[c + 1] += s[k] * vv.y;
                    acc[c + 2] += s[k] * vv.z;
                    acc[c + 3] += s[k] * vv.w;
                }
            }
        }
    }

    const float inv = 1.f / l;
    float* optr = O + ((size_t)(b * NQ + qt * 64 + r)) * DMODEL + h * DHEAD + sub * 16;
    #pragma unroll
    for (int c = 0; c < 16; c += 4) {
        float4 o;
        o.x = acc[c + 0] * inv + q[c + 0] * 8.f;
        o.y = acc[c + 1] * inv + q[c + 1] * 8.f;
        o.z = acc[c + 2] * inv + q[c + 2] * 8.f;
        o.w = acc[c + 3] * inv + q[c + 3] * 8.f;
        *(float4*)(optr + c) = o;
    }
}

// ---------------- LayerNorm over last dim (512) ----------------
__global__ __launch_bounds__(128) void ln512(
    const float* __restrict__ X, const float* __restrict__ g,
    const float* __restrict__ be, float* __restrict__ Y)
{
    const int row = blockIdx.x;
    const int tid = threadIdx.x;
    const float* x = X + (size_t)row * 512;

    float4 v = *(const float4*)(x + tid * 4);
    float s  = v.x + v.y + v.z + v.w;
    float ss = v.x * v.x + v.y * v.y + v.z * v.z + v.w * v.w;
    #pragma unroll
    for (int o = 16; o; o >>= 1) {
        s  += __shfl_xor_sync(0xffffffffu, s, o);
        ss += __shfl_xor_sync(0xffffffffu, ss, o);
    }
    __shared__ float sm[4], sm2[4];
    if ((tid & 31) == 0) { sm[tid >> 5] = s; sm2[tid >> 5] = ss; }
    __syncthreads();
    const float ts  = sm[0] + sm[1] + sm[2] + sm[3];
    const float tss = sm2[0] + sm2[1] + sm2[2] + sm2[3];
    const float mean = ts * (1.f / 512.f);
    const float var  = tss * (1.f / 512.f) - mean * mean;
    const float rstd = rsqrtf(var + 1e-5f);

    float4 gg = *(const float4*)(g + tid * 4);
    float4 bb = *(const float4*)(be + tid * 4);
    float4 o;
    o.x = (v.x - mean) * rstd * gg.x + bb.x;
    o.y = (v.y - mean) * rstd * gg.y + bb.y;
    o.z = (v.z - mean) * rstd * gg.z + bb.z;
    o.w = (v.w - mean) * rstd * gg.w + bb.w;
    *(float4*)(Y + (size_t)row * 512 + tid * 4) = o;
}

// ---------------- launch ----------------
extern "C" void kernel_launch(void* const* d_in, const int* in_sizes, int n_in,
                              void* d_out, int out_size)
{
    const float* Q  = (const float*)d_in[0];
    const float* K  = (const float*)d_in[1];
    const float* Wq = (const float*)d_in[2];
    const float* bq = (const float*)d_in[3];
    const float* Wk = (const float*)d_in[4];
    const float* bk = (const float*)d_in[5];
    const float* Wv = (const float*)d_in[6];
    const float* bv = (const float*)d_in[7];
    const float* Wo = (const float*)d_in[8];
    const float* bo = (const float*)d_in[9];
    const float* g0 = (const float*)d_in[10];
    const float* b0 = (const float*)d_in[11];
    const float* g1 = (const float*)d_in[12];
    const float* b1 = (const float*)d_in[13];
    float* out = (float*)d_out;

    float *Qp, *Kp, *Vp, *Obuf;
    __nv_bfloat16 *Ah, *Al, *Bh, *Bl, *Wth, *Wtl;
    cudaGetSymbolAddress((void**)&Qp, g_Qp);
    cudaGetSymbolAddress((void**)&Kp, g_Kp);
    cudaGetSymbolAddress((void**)&Vp, g_Vp);
    cudaGetSymbolAddress((void**)&Obuf, g_O);
    cudaGetSymbolAddress((void**)&Ah, g_Ah);
    cudaGetSymbolAddress((void**)&Al, g_Al);
    cudaGetSymbolAddress((void**)&Bh, g_Bh);
    cudaGetSymbolAddress((void**)&Bl, g_Bl);
    cudaGetSymbolAddress((void**)&Wth, g_Wth);
    cudaGetSymbolAddress((void**)&Wtl, g_Wtl);

    const int WSZ = 512 * 512;
    dim3 wtg(16, 16), wtb(32, 8);
    conv_wt<<<wtg, wtb>>>(Wq, Wth + 0 * WSZ, Wtl + 0 * WSZ);
    conv_wt<<<wtg, wtb>>>(Wk, Wth + 1 * WSZ, Wtl + 1 * WSZ);
    conv_wt<<<wtg, wtb>>>(Wv, Wth + 2 * WSZ, Wtl + 2 * WSZ);
    conv_wt<<<wtg, wtb>>>(Wo, Wth + 3 * WSZ, Wtl + 3 * WSZ);

    const int CVB = (MROWS * DMODEL / 4) / 256;   // 4096
    conv_act<<<CVB, 256>>>(Q, Ah, Al);
    conv_act<<<CVB, 256>>>(K, Bh, Bl);

    dim3 gg(DMODEL / 64, MROWS / 128);   // (8, 64)
    tc_gemm<<<gg, 256>>>(Ah, Al, Wth + 0 * WSZ, Wtl + 0 * WSZ, bq, nullptr, Qp, 0);
    tc_gemm<<<gg, 256>>>(Bh, Bl, Wth + 1 * WSZ, Wtl + 1 * WSZ, bk, nullptr, Kp, 0);
    tc_gemm<<<gg, 256>>>(Bh, Bl, Wth + 2 * WSZ, Wtl + 2 * WSZ, bv, nullptr, Vp, 0);

    attn_kernel<<<dim3(NQ / 64, NHEAD, BATCH), 256>>>(Qp, Kp, Vp, Obuf);

    ln512<<<MROWS, 128>>>(Obuf, g0, b0, Qp);           // X = LN(O)
    conv_act<<<CVB, 256>>>(Qp, Ah, Al);                // split X
    tc_gemm<<<gg, 256>>>(Ah, Al, Wth + 3 * WSZ, Wtl + 3 * WSZ, bo, Qp, Kp, 1);
    ln512<<<MROWS, 128>>>(Kp, g1, b1, out);
}

// round 4
// speedup vs baseline: 4.6348x; 4.2385x over previous
#include <cuda_runtime.h>
#include <cuda_bf16.h>
#include <cstdint>

#define BATCH 8
#define NQ 1024
#define NK 1024
#define DMODEL 512
#define NHEAD 8
#define DHEAD 64
#define MROWS (BATCH * NQ)   // 8192
#define AST 40               // gemm smem row stride in bf16 (32 data + 8 pad)

// ---------------- scratch (no allocation allowed) ----------------
__device__ float g_X [(size_t)MROWS * DMODEL];   // LN0 output
__device__ float g_Y [(size_t)MROWS * DMODEL];   // MLP output
__device__ float g_O [(size_t)MROWS * DMODEL];   // attention output
__device__ __nv_bfloat16 g_Ah[(size_t)MROWS * DMODEL];
__device__ __nv_bfloat16 g_Al[(size_t)MROWS * DMODEL];
__device__ __nv_bfloat16 g_Bh[(size_t)MROWS * DMODEL];
__device__ __nv_bfloat16 g_Bl[(size_t)MROWS * DMODEL];
__device__ __nv_bfloat16 g_PQh[(size_t)MROWS * DMODEL];
__device__ __nv_bfloat16 g_PQl[(size_t)MROWS * DMODEL];
__device__ __nv_bfloat16 g_PKh[(size_t)MROWS * DMODEL];
__device__ __nv_bfloat16 g_PKl[(size_t)MROWS * DMODEL];
__device__ __nv_bfloat16 g_PVh[(size_t)MROWS * DMODEL];
__device__ __nv_bfloat16 g_PVl[(size_t)MROWS * DMODEL];
__device__ __nv_bfloat16 g_Wth[4 * 512 * 512];   // W^T hi: [n][k]
__device__ __nv_bfloat16 g_Wtl[4 * 512 * 512];   // W^T lo: [n][k]

// ---------------- warp-mma helpers (base PTX, works on sm_103) ----------------
__device__ __forceinline__ uint32_t s2u(const void* p) {
    uint32_t a;
    asm("{ .reg .u64 t; cvta.to.shared.u64 t, %1; cvt.u32.u64 %0, t; }" : "=r"(a) : "l"(p));
    return a;
}
#define SWZ(o) ((o) ^ (((o) >> 3) & 0x70))

__device__ __forceinline__ void ldsm_x4(uint32_t* r, uint32_t addr) {
    asm volatile("ldmatrix.sync.aligned.m8n8.x4.shared.b16 {%0,%1,%2,%3}, [%4];"
                 : "=r"(r[0]), "=r"(r[1]), "=r"(r[2]), "=r"(r[3]) : "r"(addr));
}
__device__ __forceinline__ void ldsm_x4t(uint32_t* r, uint32_t addr) {
    asm volatile("ldmatrix.sync.aligned.m8n8.x4.trans.shared.b16 {%0,%1,%2,%3}, [%4];"
                 : "=r"(r[0]), "=r"(r[1]), "=r"(r[2]), "=r"(r[3]) : "r"(addr));
}
__device__ __forceinline__ void mma16816(float* d, const uint32_t* a, const uint32_t* b) {
    asm volatile(
        "mma.sync.aligned.m16n8k16.row.col.f32.bf16.bf16.f32 "
        "{%0,%1,%2,%3}, {%4,%5,%6,%7}, {%8,%9}, {%0,%1,%2,%3};"
        : "+f"(d[0]), "+f"(d[1]), "+f"(d[2]), "+f"(d[3])
        : "r"(a[0]), "r"(a[1]), "r"(a[2]), "r"(a[3]), "r"(b[0]), "r"(b[1]));
}

__device__ __forceinline__ void split_pack(float x, float y, uint32_t& ph, uint32_t& pl) {
    __nv_bfloat16 hx = __float2bfloat16(x), hy = __float2bfloat16(y);
    __nv_bfloat162 hh(hx, hy);
    ph = *(uint32_t*)&hh;
    __nv_bfloat162 ll(__float2bfloat16(x - __bfloat162float(hx)),
                      __float2bfloat16(y - __bfloat162float(hy)));
    pl = *(uint32_t*)&ll;
}

// ---------------- conversion kernels ----------------
__global__ __launch_bounds__(256) void conv_act(
    const float* __restrict__ X, __nv_bfloat16* __restrict__ H,
    __nv_bfloat16* __restrict__ L)
{
    const size_t i = (size_t)blockIdx.x * 256 + threadIdx.x;
    float4 v = ((const float4*)X)[i];
    __nv_bfloat16 h0 = __float2bfloat16(v.x), h1 = __float2bfloat16(v.y);
    __nv_bfloat16 h2 = __float2bfloat16(v.z), h3 = __float2bfloat16(v.w);
    __nv_bfloat16 l0 = __float2bfloat16(v.x - __bfloat162float(h0));
    __nv_bfloat16 l1 = __float2bfloat16(v.y - __bfloat162float(h1));
    __nv_bfloat16 l2 = __float2bfloat16(v.z - __bfloat162float(h2));
    __nv_bfloat16 l3 = __float2bfloat16(v.w - __bfloat162float(h3));
    ((__nv_bfloat162*)H)[2 * i + 0] = __nv_bfloat162(h0, h1);
    ((__nv_bfloat162*)H)[2 * i + 1] = __nv_bfloat162(h2, h3);
    ((__nv_bfloat162*)L)[2 * i + 0] = __nv_bfloat162(l0, l1);
    ((__nv_bfloat162*)L)[2 * i + 1] = __nv_bfloat162(l2, l3);
}

// W[512 k][512 n] fp32 -> Wt[512 n][512 k] bf16 hi/lo (transpose + split)
__global__ __launch_bounds__(256) void conv_wt(
    const float* __restrict__ W, __nv_bfloat16* __restrict__ Th,
    __nv_bfloat16* __restrict__ Tl)
{
    __shared__ float t[32][33];
    const int bx = blockIdx.x * 32;  // n
    const int by = blockIdx.y * 32;  // k
    const int x = threadIdx.x, y0 = threadIdx.y;
    #pragma unroll
    for (int j = 0; j < 32; j += 8)
        t[y0 + j][x] = W[(size_t)(by + y0 + j) * 512 + bx + x];
    __syncthreads();
    #pragma unroll
    for (int j = 0; j < 32; j += 8) {
        float v = t[x][y0 + j];
        __nv_bfloat16 h = __float2bfloat16(v);
        __nv_bfloat16 l = __float2bfloat16(v - __bfloat162float(h));
        const size_t o = (size_t)(bx + y0 + j) * 512 + by + x;
        Th[o] = h;
        Tl[o] = l;
    }
}

// ---------------- warp-mma GEMM ----------------
// C (or Chi/Clo split) = fp32(A) @ fp32(W) + bias; fuse: C = resid + relu(.)
__global__ __launch_bounds__(256) void tc_gemm(
    const __nv_bfloat16* __restrict__ Ah, const __nv_bfloat16* __restrict__ Al,
    const __nv_bfloat16* __restrict__ Bh, const __nv_bfloat16* __restrict__ Bl,
    const float* __restrict__ bias, const float* __restrict__ resid,
    float* __restrict__ C, __nv_bfloat16* __restrict__ Chi,
    __nv_bfloat16* __restrict__ Clo, int fuse)
{
    __shared__ __nv_bfloat16 sAh[128 * AST];
    __shared__ __nv_bfloat16 sAl[128 * AST];
    __shared__ __nv_bfloat16 sBh[64 * AST];
    __shared__ __nv_bfloat16 sBl[64 * AST];

    const int tid = threadIdx.x, wid = tid >> 5, lane = tid & 31;
    const int m0 = blockIdx.y * 128, n0 = blockIdx.x * 64;
    const int warp_m = (wid & 3) * 32, warp_n = (wid >> 2) * 32;

    float acc[2][4][4];
    #pragma unroll
    for (int mt = 0; mt < 2; mt++)
        #pragma unroll
        for (int nt = 0; nt < 4; nt++)
            #pragma unroll
            for (int i = 0; i < 4; i++) acc[mt][nt][i] = 0.f;

    const int a_row = lane & 15, a_cb = (lane >> 4) * 8;
    const int b_nof = (lane & 7) + ((lane >> 4) & 1) * 8;
    const int b_kof = ((lane >> 3) & 1) * 8;

    for (int kc = 0; kc < 16; kc++) {
        #pragma unroll
        for (int i = 0; i < 2; i++) {
            const int idx = i * 256 + tid;
            const int row = idx >> 2, c = idx & 3;
            const size_t go = (size_t)(m0 + row) * 512 + kc * 32 + c * 8;
            *(uint4*)&sAh[row * AST + c * 8] = *(const uint4*)(Ah + go);
            *(uint4*)&sAl[row * AST + c * 8] = *(const uint4*)(Al + go);
        }
        {
            const int row = tid >> 2, c = tid & 3;
            const size_t go = (size_t)(n0 + row) * 512 + kc * 32 + c * 8;
            *(uint4*)&sBh[row * AST + c * 8] = *(const uint4*)(Bh + go);
            *(uint4*)&sBl[row * AST + c * 8] = *(const uint4*)(Bl + go);
        }
        __syncthreads();

        #pragma unroll
        for (int ks = 0; ks < 2; ks++) {
            const int k16 = ks * 16;
            uint32_t afh[2][4], afl[2][4], bfh[2][4], bfl[2][4];
            #pragma unroll
            for (int mt = 0; mt < 2; mt++) {
                const int off = (warp_m + mt * 16 + a_row) * AST + k16 + a_cb;
                ldsm_x4(afh[mt], s2u(&sAh[off]));
                ldsm_x4(afl[mt], s2u(&sAl[off]));
            }
            #pragma unroll
            for (int nb = 0; nb < 2; nb++) {
                const int off = (warp_n + nb * 16 + b_nof) * AST + k16 + b_kof;
                ldsm_x4(bfh[nb], s2u(&sBh[off]));
                ldsm_x4(bfl[nb], s2u(&sBl[off]));
            }
            #pragma unroll
            for (int mt = 0; mt < 2; mt++)
                #pragma unroll
                for (int nt = 0; nt < 4; nt++) {
                    const uint32_t* bh = &bfh[nt >> 1][(nt & 1) * 2];
                    const uint32_t* bl = &bfl[nt >> 1][(nt & 1) * 2];
                    mma16816(acc[mt][nt], afh[mt], bh);
                    mma16816(acc[mt][nt], afh[mt], bl);
                    mma16816(acc[mt][nt], afl[mt], bh);
                }
        }
        __syncthreads();
    }

    const int r0 = lane >> 2, c0 = (lane & 3) * 2;
    #pragma unroll
    for (int mt = 0; mt < 2; mt++) {
        #pragma unroll
        for (int nt = 0; nt < 4; nt++) {
            const int cc = n0 + warp_n + nt * 8 + c0;
            const float2 bb = *(const float2*)(bias + cc);
            #pragma unroll
            for (int half = 0; half < 2; half++) {
                const int rr = m0 + warp_m + mt * 16 + r0 + half * 8;
                float ox = acc[mt][nt][half * 2 + 0] + bb.x;
                float oy = acc[mt][nt][half * 2 + 1] + bb.y;
                const size_t go = (size_t)rr * 512 + cc;
                if (Chi) {
                    uint32_t ph, pl;
                    split_pack(ox, oy, ph, pl);
                    *(uint32_t*)(Chi + go) = ph;
                    *(uint32_t*)(Clo + go) = pl;
                } else {
                    if (fuse) {
                        float2 xr = *(const float2*)(resid + go);
                        ox = xr.x + fmaxf(ox, 0.f);
                        oy = xr.y + fmaxf(oy, 0.f);
                    }
                    float2 o = make_float2(ox, oy);
                    *(float2*)(C + go) = o;
                }
            }
        }
    }
}

// ---------------- attention: mma flash kernel ----------------
// CTA: (qtile 128 rows, head, batch). 8 warps x 16 q-rows.
// All operands bf16 hi/lo split; S = Qh Kh + Qh Kl + Ql Kh; O += Ph Vh + Pl Vh + Ph Vl.
__global__ __launch_bounds__(256) void attn_mma(
    const __nv_bfloat16* __restrict__ Qh, const __nv_bfloat16* __restrict__ Ql,
    const __nv_bfloat16* __restrict__ Kh, const __nv_bfloat16* __restrict__ Kl,
    const __nv_bfloat16* __restrict__ Vh, const __nv_bfloat16* __restrict__ Vl,
    float* __restrict__ O)
{
    __shared__ __align__(1024) unsigned char sm[32768];

    const int qt = blockIdx.x, h = blockIdx.y, b = blockIdx.z;
    const int tid = threadIdx.x, wid = tid >> 5, lane = tid & 31;
    const int hcol = h * DHEAD;
    const size_t qbase = (size_t)(b * NQ + qt * 128);

    // ---- stage Q tile (128 x 64) hi -> sm[0:16K], lo -> sm[16K:32K]
    for (int i = tid; i < 1024; i += 256) {
        const int row = i >> 3, u = i & 7;
        const size_t g = (qbase + row) * 512 + hcol + u * 8;
        const int off = SWZ(row * 128 + u * 16);
        *(uint4*)(sm + off)         = *(const uint4*)(Qh + g);
        *(uint4*)(sm + 16384 + off) = *(const uint4*)(Ql + g);
    }
    __syncthreads();

    // ---- Q fragments (m16k16 x 4 k-tiles), kept in registers
    uint32_t qfh[4][4], qfl[4][4];
    {
        const int qrow = wid * 16 + (lane & 15);
        #pragma unroll
        for (int t = 0; t < 4; t++) {
            const int off = SWZ(qrow * 128 + (t * 16 + (lane >> 4) * 8) * 2);
            ldsm_x4(qfh[t], s2u(sm + off));
            ldsm_x4(qfl[t], s2u(sm + 16384 + off));
        }
    }
    __syncthreads();

    float m0 = -1e30f, m1 = -1e30f, l0 = 0.f, l1 = 0.f;
    float o[8][4];
    #pragma unroll
    for (int i = 0; i < 8; i++)
        #pragma unroll
        for (int j = 0; j < 4; j++) o[i][j] = 0.f;

    for (int kt = 0; kt < 16; kt++) {
        // ---- load K/V tile (64 x 64) hi/lo: Kh@0, Kl@8K, Vh@16K, Vl@24K
        for (int i = tid; i < 512; i += 256) {
            const int row = i >> 3, u = i & 7;
            const size_t g = ((size_t)(b * NK + kt * 64 + row)) * 512 + hcol + u * 8;
            const int off = SWZ(row * 128 + u * 16);
            *(uint4*)(sm + off)         = *(const uint4*)(Kh + g);
            *(uint4*)(sm + 8192 + off)  = *(const uint4*)(Kl + g);
            *(uint4*)(sm + 16384 + off) = *(const uint4*)(Vh + g);
            *(uint4*)(sm + 24576 + off) = *(const uint4*)(Vl + g);
        }
        __syncthreads();

        // ---- S = Q K^T (8 n-tiles of 8 kv each)
        float s[8][4];
        #pragma unroll
        for (int i = 0; i < 8; i++)
            #pragma unroll
            for (int j = 0; j < 4; j++) s[i][j] = 0.f;

        #pragma unroll
        for (int nb = 0; nb < 4; nb++) {
            #pragma unroll
            for (int t = 0; t < 4; t++) {
                uint32_t bh[4], bl[4];
                const int krow = nb * 16 + (lane & 7) + ((lane >> 4) & 1) * 8;
                const int off = SWZ(krow * 128 + (t * 16 + ((lane >> 3) & 1) * 8) * 2);
                ldsm_x4(bh, s2u(sm + off));
                ldsm_x4(bl, s2u(sm + 8192 + off));
                mma16816(s[2 * nb], qfh[t], bh);
                mma16816(s[2 * nb], qfh[t], bl);
                mma16816(s[2 * nb], qfl[t], bh);
                mma16816(s[2 * nb + 1], qfh[t], bh + 2);
                mma16816(s[2 * nb + 1], qfh[t], bl + 2);
                mma16816(s[2 * nb + 1], qfl[t], bh + 2);
            }
        }

        // ---- online softmax (rows r0 = lane>>2, r1 = r0+8)
        float tm0 = -1e30f, tm1 = -1e30f;
        #pragma unroll
        for (int nt = 0; nt < 8; nt++) {
            #pragma unroll
            for (int j = 0; j < 4; j++) s[nt][j] *= 0.125f;
            tm0 = fmaxf(tm0, fmaxf(s[nt][0], s[nt][1]));
            tm1 = fmaxf(tm1, fmaxf(s[nt][2], s[nt][3]));
        }
        tm0 = fmaxf(tm0, __shfl_xor_sync(0xffffffffu, tm0, 1));
        tm0 = fmaxf(tm0, __shfl_xor_sync(0xffffffffu, tm0, 2));
        tm1 = fmaxf(tm1, __shfl_xor_sync(0xffffffffu, tm1, 1));
        tm1 = fmaxf(tm1, __shfl_xor_sync(0xffffffffu, tm1, 2));

        const float mn0 = fmaxf(m0, tm0), mn1 = fmaxf(m1, tm1);
        const float cr0 = __expf(m0 - mn0), cr1 = __expf(m1 - mn1);
        m0 = mn0; m1 = mn1;
        #pragma unroll
        for (int i = 0; i < 8; i++) {
            o[i][0] *= cr0; o[i][1] *= cr0;
            o[i][2] *= cr1; o[i][3] *= cr1;
        }
        float rs0 = 0.f, rs1 = 0.f;
        #pragma unroll
        for (int nt = 0; nt < 8; nt++) {
            s[nt][0] = __expf(s[nt][0] - mn0);
            s[nt][1] = __expf(s[nt][1] - mn0);
            s[nt][2] = __expf(s[nt][2] - mn1);
            s[nt][3] = __expf(s[nt][3] - mn1);
            rs0 += s[nt][0] + s[nt][1];
            rs1 += s[nt][2] + s[nt][3];
        }
        rs0 += __shfl_xor_sync(0xffffffffu, rs0, 1);
        rs0 += __shfl_xor_sync(0xffffffffu, rs0, 2);
        rs1 += __shfl_xor_sync(0xffffffffu, rs1, 1);
        rs1 += __shfl_xor_sync(0xffffffffu, rs1, 2);
        l0 = l0 * cr0 + rs0;
        l1 = l1 * cr1 + rs1;

        // ---- O += P V (P split hi/lo)
        #pragma unroll
        for (int j = 0; j < 4; j++) {
            uint32_t ah[4], al[4];
            split_pack(s[2 * j][0], s[2 * j][1], ah[0], al[0]);
            split_pack(s[2 * j][2], s[2 * j][3], ah[1], al[1]);
            split_pack(s[2 * j + 1][0], s[2 * j + 1][1], ah[2], al[2]);
            split_pack(s[2 * j + 1][2], s[2 * j + 1][3], ah[3], al[3]);
            const int vrow = j * 16 + (lane & 15);
            #pragma unroll
            for (int nb = 0; nb < 4; nb++) {
                uint32_t vh[4], vl[4];
                const int off = SWZ(vrow * 128 + (nb * 16 + (lane >> 4) * 8) * 2);
                ldsm_x4t(vh, s2u(sm + 16384 + off));
                ldsm_x4t(vl, s2u(sm + 24576 + off));
                mma16816(o[2 * nb], ah, vh);
                mma16816(o[2 * nb], al, vh);
                mma16816(o[2 * nb], ah, vl);
                mma16816(o[2 * nb + 1], ah, vh + 2);
                mma16816(o[2 * nb + 1], al, vh + 2);
                mma16816(o[2 * nb + 1], ah, vl + 2);
            }
        }
        __syncthreads();
    }

    // ---- epilogue: normalize + residual (Qh+Ql) -> O fp32
    const float inv0 = 1.f / l0, inv1 = 1.f / l1;
    const int row0 = wid * 16 + (lane >> 2);
    #pragma unroll
    for (int nt = 0; nt < 8; nt++) {
        const int col = hcol + nt * 8 + (lane & 3) * 2;
        #pragma unroll
        for (int half = 0; half < 2; half++) {
            const size_t g = (qbase + row0 + half * 8) * 512 + col;
            __nv_bfloat162 qh2 = *(const __nv_bfloat162*)(Qh + g);
            __nv_bfloat162 ql2 = *(const __nv_bfloat162*)(Ql + g);
            const float inv = half ? inv1 : inv0;
            float2 out;
            out.x = o[nt][half * 2 + 0] * inv + __bfloat162float(qh2.x) + __bfloat162float(ql2.x);
            out.y = o[nt][half * 2 + 1] * inv + __bfloat162float(qh2.y) + __bfloat162float(ql2.y);
            *(float2*)(O + g) = out;
        }
    }
}

// ---------------- LayerNorm over last dim (512) ----------------
__global__ __launch_bounds__(128) void ln512(
    const float* __restrict__ X, const float* __restrict__ g,
    const float* __restrict__ be, float* __restrict__ Y)
{
    const int row = blockIdx.x;
    const int tid = threadIdx.x;
    const float* x = X + (size_t)row * 512;

    float4 v = *(const float4*)(x + tid * 4);
    float s  = v.x + v.y + v.z + v.w;
    float ss = v.x * v.x + v.y * v.y + v.z * v.z + v.w * v.w;
    #pragma unroll
    for (int o = 16; o; o >>= 1) {
        s  += __shfl_xor_sync(0xffffffffu, s, o);
        ss += __shfl_xor_sync(0xffffffffu, ss, o);
    }
    __shared__ float sm[4], sm2[4];
    if ((tid & 31) == 0) { sm[tid >> 5] = s; sm2[tid >> 5] = ss; }
    __syncthreads();
    const float ts  = sm[0] + sm[1] + sm[2] + sm[3];
    const float tss = sm2[0] + sm2[1] + sm2[2] + sm2[3];
    const float mean = ts * (1.f / 512.f);
    const float var  = tss * (1.f / 512.f) - mean * mean;
    const float rstd = rsqrtf(var + 1e-5f);

    float4 gg = *(const float4*)(g + tid * 4);
    float4 bb = *(const float4*)(be + tid * 4);
    float4 o;
    o.x = (v.x - mean) * rstd * gg.x + bb.x;
    o.y = (v.y - mean) * rstd * gg.y + bb.y;
    o.z = (v.z - mean) * rstd * gg.z + bb.z;
    o.w = (v.w - mean) * rstd * gg.w + bb.w;
    *(float4*)(Y + (size_t)row * 512 + tid * 4) = o;
}

// ---------------- launch ----------------
extern "C" void kernel_launch(void* const* d_in, const int* in_sizes, int n_in,
                              void* d_out, int out_size)
{
    const float* Q  = (const float*)d_in[0];
    const float* K  = (const float*)d_in[1];
    const float* Wq = (const float*)d_in[2];
    const float* bq = (const float*)d_in[3];
    const float* Wk = (const float*)d_in[4];
    const float* bk = (const float*)d_in[5];
    const float* Wv = (const float*)d_in[6];
    const float* bv = (const float*)d_in[7];
    const float* Wo = (const float*)d_in[8];
    const float* bo = (const float*)d_in[9];
    const float* g0 = (const float*)d_in[10];
    const float* b0 = (const float*)d_in[11];
    const float* g1 = (const float*)d_in[12];
    const float* b1 = (const float*)d_in[13];
    float* out = (float*)d_out;

    float *X, *Y, *Obuf;
    __nv_bfloat16 *Ah, *Al, *Bh, *Bl, *Wth, *Wtl;
    __nv_bfloat16 *PQh, *PQl, *PKh, *PKl, *PVh, *PVl;
    cudaGetSymbolAddress((void**)&X, g_X);
    cudaGetSymbolAddress((void**)&Y, g_Y);
    cudaGetSymbolAddress((void**)&Obuf, g_O);
    cudaGetSymbolAddress((void**)&Ah, g_Ah);
    cudaGetSymbolAddress((void**)&Al, g_Al);
    cudaGetSymbolAddress((void**)&Bh, g_Bh);
    cudaGetSymbolAddress((void**)&Bl, g_Bl);
    cudaGetSymbolAddress((void**)&PQh, g_PQh);
    cudaGetSymbolAddress((void**)&PQl, g_PQl);
    cudaGetSymbolAddress((void**)&PKh, g_PKh);
    cudaGetSymbolAddress((void**)&PKl, g_PKl);
    cudaGetSymbolAddress((void**)&PVh, g_PVh);
    cudaGetSymbolAddress((void**)&PVl, g_PVl);
    cudaGetSymbolAddress((void**)&Wth, g_Wth);
    cudaGetSymbolAddress((void**)&Wtl, g_Wtl);

    const int WSZ = 512 * 512;
    dim3 wtg(16, 16), wtb(32, 8);
    conv_wt<<<wtg, wtb>>>(Wq, Wth + 0 * WSZ, Wtl + 0 * WSZ);
    conv_wt<<<wtg, wtb>>>(Wk, Wth + 1 * WSZ, Wtl + 1 * WSZ);
    conv_wt<<<wtg, wtb>>>(Wv, Wth + 2 * WSZ, Wtl + 2 * WSZ);
    conv_wt<<<wtg, wtb>>>(Wo, Wth + 3 * WSZ, Wtl + 3 * WSZ);

    const int CVB = (MROWS * DMODEL / 4) / 256;   // 4096
    conv_act<<<CVB, 256>>>(Q, Ah, Al);
    conv_act<<<CVB, 256>>>(K, Bh, Bl);

    dim3 gg(DMODEL / 64, MROWS / 128);   // (8, 64)
    tc_gemm<<<gg, 256>>>(Ah, Al, Wth + 0 * WSZ, Wtl + 0 * WSZ, bq, nullptr,
                         nullptr, PQh, PQl, 0);
    tc_gemm<<<gg, 256>>>(Bh, Bl, Wth + 1 * WSZ, Wtl + 1 * WSZ, bk, nullptr,
                         nullptr, PKh, PKl, 0);
    tc_gemm<<<gg, 256>>>(Bh, Bl, Wth + 2 * WSZ, Wtl + 2 * WSZ, bv, nullptr,
                         nullptr, PVh, PVl, 0);

    attn_mma<<<dim3(NQ / 128, NHEAD, BATCH), 256>>>(PQh, PQl, PKh, PKl, PVh, PVl, Obuf);

    ln512<<<MROWS, 128>>>(Obuf, g0, b0, X);
    conv_act<<<CVB, 256>>>(X, Ah, Al);
    tc_gemm<<<gg, 256>>>(Ah, Al, Wth + 3 * WSZ, Wtl + 3 * WSZ, bo, X,
                         Y, nullptr, nullptr, 1);
    ln512<<<MROWS, 128>>>(Y, g1, b1, out);
}

// round 5
// speedup vs baseline: 6.1821x; 1.3338x over previous
#include <cuda_runtime.h>
#include <cuda_bf16.h>
#include <cstdint>

#define BATCH 8
#define NQ 1024
#define NK 1024
#define DMODEL 512
#define NHEAD 8
#define DHEAD 64
#define MROWS (BATCH * NQ)   // 8192
#define AST 40               // gemm smem row stride in bf16 (32 data + 8 pad)

typedef __nv_bfloat16 bf16;

// ---------------- scratch (no allocation allowed) ----------------
__device__ float g_X [(size_t)MROWS * DMODEL];   // LN0 output (fp32, resid for MLP)
__device__ float g_Y [(size_t)MROWS * DMODEL];   // MLP output
__device__ float g_O [(size_t)MROWS * DMODEL];   // attention output
__device__ bf16 g_Ah[(size_t)MROWS * DMODEL];
__device__ bf16 g_Al[(size_t)MROWS * DMODEL];
__device__ bf16 g_Bh[(size_t)MROWS * DMODEL];
__device__ bf16 g_Bl[(size_t)MROWS * DMODEL];
__device__ bf16 g_PQh[(size_t)MROWS * DMODEL];
__device__ bf16 g_PQl[(size_t)MROWS * DMODEL];
__device__ bf16 g_PKh[(size_t)MROWS * DMODEL];
__device__ bf16 g_PKl[(size_t)MROWS * DMODEL];
__device__ bf16 g_PVh[(size_t)MROWS * DMODEL];
__device__ bf16 g_PVl[(size_t)MROWS * DMODEL];
__device__ bf16 g_Wth[4 * 512 * 512];   // W^T hi: [n][k]
__device__ bf16 g_Wtl[4 * 512 * 512];   // W^T lo: [n][k]

// ---------------- helpers (base PTX, works on sm_103) ----------------
__device__ __forceinline__ uint32_t s2u(const void* p) {
    uint32_t a;
    asm("{ .reg .u64 t; cvta.to.shared.u64 t, %1; cvt.u32.u64 %0, t; }" : "=r"(a) : "l"(p));
    return a;
}
#define SWZ(o) ((o) ^ (((o) >> 3) & 0x70))

__device__ __forceinline__ void cpa16(uint32_t s, const void* g) {
    asm volatile("cp.async.cg.shared.global [%0], [%1], 16;" :: "r"(s), "l"(g));
}
#define CP_COMMIT() asm volatile("cp.async.commit_group;")
#define CP_WAIT0()  asm volatile("cp.async.wait_group 0;")

__device__ __forceinline__ void ldsm_x4(uint32_t* r, uint32_t addr) {
    asm volatile("ldmatrix.sync.aligned.m8n8.x4.shared.b16 {%0,%1,%2,%3}, [%4];"
                 : "=r"(r[0]), "=r"(r[1]), "=r"(r[2]), "=r"(r[3]) : "r"(addr));
}
__device__ __forceinline__ void ldsm_x4t(uint32_t* r, uint32_t addr) {
    asm volatile("ldmatrix.sync.aligned.m8n8.x4.trans.shared.b16 {%0,%1,%2,%3}, [%4];"
                 : "=r"(r[0]), "=r"(r[1]), "=r"(r[2]), "=r"(r[3]) : "r"(addr));
}
__device__ __forceinline__ void mma16816(float* d, const uint32_t* a, const uint32_t* b) {
    asm volatile(
        "mma.sync.aligned.m16n8k16.row.col.f32.bf16.bf16.f32 "
        "{%0,%1,%2,%3}, {%4,%5,%6,%7}, {%8,%9}, {%0,%1,%2,%3};"
        : "+f"(d[0]), "+f"(d[1]), "+f"(d[2]), "+f"(d[3])
        : "r"(a[0]), "r"(a[1]), "r"(a[2]), "r"(a[3]), "r"(b[0]), "r"(b[1]));
}
__device__ __forceinline__ void split_pack(float x, float y, uint32_t& ph, uint32_t& pl) {
    bf16 hx = __float2bfloat16(x), hy = __float2bfloat16(y);
    __nv_bfloat162 hh(hx, hy);
    ph = *(uint32_t*)&hh;
    __nv_bfloat162 ll(__float2bfloat16(x - __bfloat162float(hx)),
                      __float2bfloat16(y - __bfloat162float(hy)));
    pl = *(uint32_t*)&ll;
}

// ---------------- conversion kernels (merged grids) ----------------
// z=0: Q -> Ah/Al ; z=1: K -> Bh/Bl
__global__ __launch_bounds__(256) void conv_act2(
    const float* __restrict__ Q, const float* __restrict__ K,
    bf16* __restrict__ Ah, bf16* __restrict__ Al,
    bf16* __restrict__ Bh, bf16* __restrict__ Bl)
{
    const float* X = blockIdx.y ? K : Q;
    bf16* H = blockIdx.y ? Bh : Ah;
    bf16* L = blockIdx.y ? Bl : Al;
    const size_t i = (size_t)blockIdx.x * 256 + threadIdx.x;
    float4 v = ((const float4*)X)[i];
    bf16 h0 = __float2bfloat16(v.x), h1 = __float2bfloat16(v.y);
    bf16 h2 = __float2bfloat16(v.z), h3 = __float2bfloat16(v.w);
    bf16 l0 = __float2bfloat16(v.x - __bfloat162float(h0));
    bf16 l1 = __float2bfloat16(v.y - __bfloat162float(h1));
    bf16 l2 = __float2bfloat16(v.z - __bfloat162float(h2));
    bf16 l3 = __float2bfloat16(v.w - __bfloat162float(h3));
    ((__nv_bfloat162*)H)[2 * i + 0] = __nv_bfloat162(h0, h1);
    ((__nv_bfloat162*)H)[2 * i + 1] = __nv_bfloat162(h2, h3);
    ((__nv_bfloat162*)L)[2 * i + 0] = __nv_bfloat162(l0, l1);
    ((__nv_bfloat162*)L)[2 * i + 1] = __nv_bfloat162(l2, l3);
}

// 4 weights transpose+split in one launch (z selects)
__global__ __launch_bounds__(256) void conv_wt4(
    const float* __restrict__ W0, const float* __restrict__ W1,
    const float* __restrict__ W2, const float* __restrict__ W3,
    bf16* __restrict__ Th, bf16* __restrict__ Tl)
{
    const int z = blockIdx.z;
    const float* W = (z == 0) ? W0 : (z == 1) ? W1 : (z == 2) ? W2 : W3;
    bf16* ThZ = Th + (size_t)z * 512 * 512;
    bf16* TlZ = Tl + (size_t)z * 512 * 512;
    __shared__ float t[32][33];
    const int bx = blockIdx.x * 32;  // n
    const int by = blockIdx.y * 32;  // k
    const int x = threadIdx.x, y0 = threadIdx.y;
    #pragma unroll
    for (int j = 0; j < 32; j += 8)
        t[y0 + j][x] = W[(size_t)(by + y0 + j) * 512 + bx + x];
    __syncthreads();
    #pragma unroll
    for (int j = 0; j < 32; j += 8) {
        float v = t[x][y0 + j];
        bf16 h = __float2bfloat16(v);
        bf16 l = __float2bfloat16(v - __bfloat162float(h));
        const size_t o = (size_t)(bx + y0 + j) * 512 + by + x;
        ThZ[o] = h;
        TlZ[o] = l;
    }
}

// ---------------- GEMM core (cp.async double-buffered) ----------------
// stage layout (bytes): sAh@0 (10240), sAl@10240, sBh@20480 (5120), sBl@25600 ; stage stride 30720
#define GSTG 30720
__device__ __forceinline__ void gemm_core(
    const bf16* __restrict__ Ah, const bf16* __restrict__ Al,
    const bf16* __restrict__ Bh, const bf16* __restrict__ Bl,
    const float* __restrict__ bias, const float* __restrict__ resid,
    float* __restrict__ C, bf16* __restrict__ Chi, bf16* __restrict__ Clo,
    int fuse, char* smem, int m0, int n0)
{
    const int tid = threadIdx.x, wid = tid >> 5, lane = tid & 31;
    const int warp_m = (wid & 3) * 32, warp_n = (wid >> 2) * 32;
    const uint32_t sb = s2u(smem);

    float acc[2][4][4];
    #pragma unroll
    for (int mt = 0; mt < 2; mt++)
        #pragma unroll
        for (int nt = 0; nt < 4; nt++)
            #pragma unroll
            for (int i = 0; i < 4; i++) acc[mt][nt][i] = 0.f;

    // per-thread load coords
    const int la_row0 = tid >> 2, la_c = tid & 3;               // A: rows tid>>2 and +64
    const int lb_row = tid >> 2, lb_c = tid & 3;                // B: 64 rows

    auto issue = [&](int kc, int stg) {
        const uint32_t base = sb + stg * GSTG;
        #pragma unroll
        for (int i = 0; i < 2; i++) {
            const int row = la_row0 + i * 64;
            const size_t go = (size_t)(m0 + row) * 512 + kc * 32 + la_c * 8;
            const uint32_t so = row * (AST * 2) + la_c * 16;
            cpa16(base + so, Ah + go);
            cpa16(base + 10240 + so, Al + go);
        }
        {
            const size_t go = (size_t)(n0 + lb_row) * 512 + kc * 32 + lb_c * 8;
            const uint32_t so = lb_row * (AST * 2) + lb_c * 16;
            cpa16(base + 20480 + so, Bh + go);
            cpa16(base + 25600 + so, Bl + go);
        }
        CP_COMMIT();
    };

    issue(0, 0);
    CP_WAIT0();
    __syncthreads();

    const int a_row = lane & 15, a_cb = (lane >> 4) * 8;
    const int b_nof = (lane & 7) + ((lane >> 4) & 1) * 8;
    const int b_kof = ((lane >> 3) & 1) * 8;

    for (int kc = 0; kc < 16; kc++) {
        const int cur = kc & 1;
        if (kc < 15) issue(kc + 1, cur ^ 1);
        const uint32_t base = sb + cur * GSTG;

        #pragma unroll
        for (int ks = 0; ks < 2; ks++) {
            const int k16 = ks * 16;
            uint32_t afh[2][4], afl[2][4], bfh[2][4], bfl[2][4];
            #pragma unroll
            for (int mt = 0; mt < 2; mt++) {
                const uint32_t off = (warp_m + mt * 16 + a_row) * (AST * 2) + (k16 + a_cb) * 2;
                ldsm_x4(afh[mt], base + off);
                ldsm_x4(afl[mt], base + 10240 + off);
            }
            #pragma unroll
            for (int nb = 0; nb < 2; nb++) {
                const uint32_t off = (warp_n + nb * 16 + b_nof) * (AST * 2) + (k16 + b_kof) * 2;
                ldsm_x4(bfh[nb], base + 20480 + off);
                ldsm_x4(bfl[nb], base + 25600 + off);
            }
            #pragma unroll
            for (int mt = 0; mt < 2; mt++)
                #pragma unroll
                for (int nt = 0; nt < 4; nt++) {
                    const uint32_t* bh = &bfh[nt >> 1][(nt & 1) * 2];
                    const uint32_t* bl = &bfl[nt >> 1][(nt & 1) * 2];
                    mma16816(acc[mt][nt], afh[mt], bh);
                    mma16816(acc[mt][nt], afh[mt], bl);
                    mma16816(acc[mt][nt], afl[mt], bh);
                }
        }
        CP_WAIT0();
        __syncthreads();
    }

    const int r0 = lane >> 2, c0 = (lane & 3) * 2;
    #pragma unroll
    for (int mt = 0; mt < 2; mt++) {
        #pragma unroll
        for (int nt = 0; nt < 4; nt++) {
            const int cc = n0 + warp_n + nt * 8 + c0;
            const float2 bb = *(const float2*)(bias + cc);
            #pragma unroll
            for (int half = 0; half < 2; half++) {
                const int rr = m0 + warp_m + mt * 16 + r0 + half * 8;
                float ox = acc[mt][nt][half * 2 + 0] + bb.x;
                float oy = acc[mt][nt][half * 2 + 1] + bb.y;
                const size_t go = (size_t)rr * 512 + cc;
                if (Chi) {
                    uint32_t ph, pl;
                    split_pack(ox, oy, ph, pl);
                    *(uint32_t*)(Chi + go) = ph;
                    *(uint32_t*)(Clo + go) = pl;
                } else {
                    if (fuse) {
                        float2 xr = *(const float2*)(resid + go);
                        ox = xr.x + fmaxf(ox, 0.f);
                        oy = xr.y + fmaxf(oy, 0.f);
                    }
                    *(float2*)(C + go) = make_float2(ox, oy);
                }
            }
        }
    }
}

// 3 projection GEMMs in one launch: z=0 Q-proj, z=1 K-proj, z=2 V-proj
__global__ __launch_bounds__(256) void proj3_gemm(
    const bf16* __restrict__ QAh, const bf16* __restrict__ QAl,
    const bf16* __restrict__ KAh, const bf16* __restrict__ KAl,
    const bf16* __restrict__ Wth, const bf16* __restrict__ Wtl,
    const float* __restrict__ bq, const float* __restrict__ bk,
    const float* __restrict__ bv,
    bf16* __restrict__ PQh, bf16* __restrict__ PQl,
    bf16* __restrict__ PKh, bf16* __restrict__ PKl,
    bf16* __restrict__ PVh, bf16* __restrict__ PVl)
{
    extern __shared__ char smem[];
    const int z = blockIdx.z;
    const bf16* Ah = (z == 0) ? QAh : KAh;
    const bf16* Al = (z == 0) ? QAl : KAl;
    const bf16* Bh = Wth + (size_t)z * 512 * 512;
    const bf16* Bl = Wtl + (size_t)z * 512 * 512;
    const float* bias = (z == 0) ? bq : (z == 1) ? bk : bv;
    bf16* Chi = (z == 0) ? PQh : (z == 1) ? PKh : PVh;
    bf16* Clo = (z == 0) ? PQl : (z == 1) ? PKl : PVl;
    gemm_core(Ah, Al, Bh, Bl, bias, nullptr, nullptr, Chi, Clo, 0, smem,
              blockIdx.y * 128, blockIdx.x * 64);
}

// MLP GEMM: Y = X + relu(X @ Wo + bo)
__global__ __launch_bounds__(256) void mlp_gemm(
    const bf16* __restrict__ Ah, const bf16* __restrict__ Al,
    const bf16* __restrict__ Bh, const bf16* __restrict__ Bl,
    const float* __restrict__ bias, const float* __restrict__ resid,
    float* __restrict__ C)
{
    extern __shared__ char smem[];
    gemm_core(Ah, Al, Bh, Bl, bias, resid, C, nullptr, nullptr, 1, smem,
              blockIdx.y * 128, blockIdx.x * 64);
}

// ---------------- attention: mma flash kernel (cp.async pipelined) ----------------
// dynamic smem: 2 stages x 32768 (Kh@0, Kl@8192, Vh@16384, Vl@24576)
__global__ __launch_bounds__(256) void attn_mma(
    const bf16* __restrict__ Qh, const bf16* __restrict__ Ql,
    const bf16* __restrict__ Kh, const bf16* __restrict__ Kl,
    const bf16* __restrict__ Vh, const bf16* __restrict__ Vl,
    float* __restrict__ O)
{
    extern __shared__ __align__(1024) char sm[];
    const uint32_t sb = s2u(sm);

    const int qt = blockIdx.x, h = blockIdx.y, b = blockIdx.z;
    const int tid = threadIdx.x, wid = tid >> 5, lane = tid & 31;
    const int hcol = h * DHEAD;
    const size_t qbase = (size_t)(b * NQ + qt * 128);

    // ---- stage Q tile (128 x 64) hi -> sm[0:16K], lo -> sm[16K:32K]
    for (int i = tid; i < 1024; i += 256) {
        const int row = i >> 3, u = i & 7;
        const size_t g = (qbase + row) * 512 + hcol + u * 8;
        const int off = SWZ(row * 128 + u * 16);
        *(uint4*)(sm + off)         = *(const uint4*)(Qh + g);
        *(uint4*)(sm + 16384 + off) = *(const uint4*)(Ql + g);
    }
    __syncthreads();

    uint32_t qfh[4][4], qfl[4][4];
    {
        const int qrow = wid * 16 + (lane & 15);
        #pragma unroll
        for (int t = 0; t < 4; t++) {
            const int off = SWZ(qrow * 128 + (t * 16 + (lane >> 4) * 8) * 2);
            ldsm_x4(qfh[t], sb + off);
            ldsm_x4(qfl[t], sb + 16384 + off);
        }
    }
    __syncthreads();

    // cp.async issue for a kv tile
    const int l_row = tid >> 3, l_u = tid & 7;   // 32 rows per pass, 2 passes
    auto issue = [&](int kt, int stg) {
        const uint32_t base = sb + stg * 32768;
        #pragma unroll
        for (int i = 0; i < 2; i++) {
            const int row = l_row + i * 32;
            const size_t g = ((size_t)(b * NK + kt * 64 + row)) * 512 + hcol + l_u * 8;
            const uint32_t off = SWZ(row * 128 + l_u * 16);
            cpa16(base + off, Kh + g);
            cpa16(base + 8192 + off, Kl + g);
            cpa16(base + 16384 + off, Vh + g);
            cpa16(base + 24576 + off, Vl + g);
        }
        CP_COMMIT();
    };

    float m0 = -1e30f, m1 = -1e30f, l0 = 0.f, l1 = 0.f;
    float o[8][4];
    #pragma unroll
    for (int i = 0; i < 8; i++)
        #pragma unroll
        for (int j = 0; j < 4; j++) o[i][j] = 0.f;

    issue(0, 0);
    CP_WAIT0();
    __syncthreads();

    for (int kt = 0; kt < 16; kt++) {
        const int cur = kt & 1;
        if (kt < 15) issue(kt + 1, cur ^ 1);
        const uint32_t base = sb + cur * 32768;

        // ---- S = Q K^T
        float s[8][4];
        #pragma unroll
        for (int i = 0; i < 8; i++)
            #pragma unroll
            for (int j = 0; j < 4; j++) s[i][j] = 0.f;

        #pragma unroll
        for (int nb = 0; nb < 4; nb++) {
            #pragma unroll
            for (int t = 0; t < 4; t++) {
                uint32_t bh[4], bl[4];
                const int krow = nb * 16 + (lane & 7) + ((lane >> 4) & 1) * 8;
                const uint32_t off = SWZ(krow * 128 + (t * 16 + ((lane >> 3) & 1) * 8) * 2);
                ldsm_x4(bh, base + off);
                ldsm_x4(bl, base + 8192 + off);
                mma16816(s[2 * nb], qfh[t], bh);
                mma16816(s[2 * nb], qfh[t], bl);
                mma16816(s[2 * nb], qfl[t], bh);
                mma16816(s[2 * nb + 1], qfh[t], bh + 2);
                mma16816(s[2 * nb + 1], qfh[t], bl + 2);
                mma16816(s[2 * nb + 1], qfl[t], bh + 2);
            }
        }

        // ---- online softmax
        float tm0 = -1e30f, tm1 = -1e30f;
        #pragma unroll
        for (int nt = 0; nt < 8; nt++) {
            #pragma unroll
            for (int j = 0; j < 4; j++) s[nt][j] *= 0.125f;
            tm0 = fmaxf(tm0, fmaxf(s[nt][0], s[nt][1]));
            tm1 = fmaxf(tm1, fmaxf(s[nt][2], s[nt][3]));
        }
        tm0 = fmaxf(tm0, __shfl_xor_sync(0xffffffffu, tm0, 1));
        tm0 = fmaxf(tm0, __shfl_xor_sync(0xffffffffu, tm0, 2));
        tm1 = fmaxf(tm1, __shfl_xor_sync(0xffffffffu, tm1, 1));
        tm1 = fmaxf(tm1, __shfl_xor_sync(0xffffffffu, tm1, 2));

        const float mn0 = fmaxf(m0, tm0), mn1 = fmaxf(m1, tm1);
        const float cr0 = __expf(m0 - mn0), cr1 = __expf(m1 - mn1);
        m0 = mn0; m1 = mn1;
        #pragma unroll
        for (int i = 0; i < 8; i++) {
            o[i][0] *= cr0; o[i][1] *= cr0;
            o[i][2] *= cr1; o[i][3] *= cr1;
        }
        float rs0 = 0.f, rs1 = 0.f;
        #pragma unroll
        for (int nt = 0; nt < 8; nt++) {
            s[nt][0] = __expf(s[nt][0] - mn0);
            s[nt][1] = __expf(s[nt][1] - mn0);
            s[nt][2] = __expf(s[nt][2] - mn1);
            s[nt][3] = __expf(s[nt][3] - mn1);
            rs0 += s[nt][0] + s[nt][1];
            rs1 += s[nt][2] + s[nt][3];
        }
        rs0 += __shfl_xor_sync(0xffffffffu, rs0, 1);
        rs0 += __shfl_xor_sync(0xffffffffu, rs0, 2);
        rs1 += __shfl_xor_sync(0xffffffffu, rs1, 1);
        rs1 += __shfl_xor_sync(0xffffffffu, rs1, 2);
        l0 = l0 * cr0 + rs0;
        l1 = l1 * cr1 + rs1;

        // ---- O += P V (P split hi/lo)
        #pragma unroll
        for (int j = 0; j < 4; j++) {
            uint32_t ah[4], al[4];
            split_pack(s[2 * j][0], s[2 * j][1], ah[0], al[0]);
            split_pack(s[2 * j][2], s[2 * j][3], ah[1], al[1]);
            split_pack(s[2 * j + 1][0], s[2 * j + 1][1], ah[2], al[2]);
            split_pack(s[2 * j + 1][2], s[2 * j + 1][3], ah[3], al[3]);
            const int vrow = j * 16 + (lane & 15);
            #pragma unroll
            for (int nb = 0; nb < 4; nb++) {
                uint32_t vh[4], vl[4];
                const uint32_t off = SWZ(vrow * 128 + (nb * 16 + (lane >> 4) * 8) * 2);
                ldsm_x4t(vh, base + 16384 + off);
                ldsm_x4t(vl, base + 24576 + off);
                mma16816(o[2 * nb], ah, vh);
                mma16816(o[2 * nb], al, vh);
                mma16816(o[2 * nb], ah, vl);
                mma16816(o[2 * nb + 1], ah, vh + 2);
                mma16816(o[2 * nb + 1], al, vh + 2);
                mma16816(o[2 * nb + 1], ah, vl + 2);
            }
        }
        CP_WAIT0();
        __syncthreads();
    }

    // ---- epilogue: normalize + residual (Qh+Ql)
    const float inv0 = 1.f / l0, inv1 = 1.f / l1;
    const int row0 = wid * 16 + (lane >> 2);
    #pragma unroll
    for (int nt = 0; nt < 8; nt++) {
        const int col = hcol + nt * 8 + (lane & 3) * 2;
        #pragma unroll
        for (int half = 0; half < 2; half++) {
            const size_t g = (qbase + row0 + half * 8) * 512 + col;
            __nv_bfloat162 qh2 = *(const __nv_bfloat162*)(Qh + g);
            __nv_bfloat162 ql2 = *(const __nv_bfloat162*)(Ql + g);
            const float inv = half ? inv1 : inv0;
            float2 out;
            out.x = o[nt][half * 2 + 0] * inv + __bfloat162float(qh2.x) + __bfloat162float(ql2.x);
            out.y = o[nt][half * 2 + 1] * inv + __bfloat162float(qh2.y) + __bfloat162float(ql2.y);
            *(float2*)(O + g) = out;
        }
    }
}

// ---------------- LayerNorm (optionally with bf16 hi/lo split output) ----------------
template <int SPLIT>
__global__ __launch_bounds__(128) void ln512(
    const float* __restrict__ X, const float* __restrict__ g,
    const float* __restrict__ be, float* __restrict__ Y,
    bf16* __restrict__ H, bf16* __restrict__ L)
{
    const int row = blockIdx.x;
    const int tid = threadIdx.x;
    const float* x = X + (size_t)row * 512;

    float4 v = *(const float4*)(x + tid * 4);
    float s  = v.x + v.y + v.z + v.w;
    float ss = v.x * v.x + v.y * v.y + v.z * v.z + v.w * v.w;
    #pragma unroll
    for (int o = 16; o; o >>= 1) {
        s  += __shfl_xor_sync(0xffffffffu, s, o);
        ss += __shfl_xor_sync(0xffffffffu, ss, o);
    }
    __shared__ float sm[4], sm2[4];
    if ((tid & 31) == 0) { sm[tid >> 5] = s; sm2[tid >> 5] = ss; }
    __syncthreads();
    const float ts  = sm[0] + sm[1] + sm[2] + sm[3];
    const float tss = sm2[0] + sm2[1] + sm2[2] + sm2[3];
    const float mean = ts * (1.f / 512.f);
    const float var  = tss * (1.f / 512.f) - mean * mean;
    const float rstd = rsqrtf(var + 1e-5f);

    float4 gg = *(const float4*)(g + tid * 4);
    float4 bb = *(const float4*)(be + tid * 4);
    float4 o;
    o.x = (v.x - mean) * rstd * gg.x + bb.x;
    o.y = (v.y - mean) * rstd * gg.y + bb.y;
    o.z = (v.z - mean) * rstd * gg.z + bb.z;
    o.w = (v.w - mean) * rstd * gg.w + bb.w;
    *(float4*)(Y + (size_t)row * 512 + tid * 4) = o;
    if (SPLIT) {
        uint32_t ph0, pl0, ph1, pl1;
        split_pack(o.x, o.y, ph0, pl0);
        split_pack(o.z, o.w, ph1, pl1);
        const size_t go = (size_t)row * 512 + tid * 4;
        *(uint32_t*)(H + go)     = ph0;
        *(uint32_t*)(H + go + 2) = ph1;
        *(uint32_t*)(L + go)     = pl0;
        *(uint32_t*)(L + go + 2) = pl1;
    }
}

// ---------------- launch ----------------
extern "C" void kernel_launch(void* const* d_in, const int* in_sizes, int n_in,
                              void* d_out, int out_size)
{
    const float* Q  = (const float*)d_in[0];
    const float* K  = (const float*)d_in[1];
    const float* Wq = (const float*)d_in[2];
    const float* bq = (const float*)d_in[3];
    const float* Wk = (const float*)d_in[4];
    const float* bk = (const float*)d_in[5];
    const float* Wv = (const float*)d_in[6];
    const float* bv = (const float*)d_in[7];
    const float* Wo = (const float*)d_in[8];
    const float* bo = (const float*)d_in[9];
    const float* g0 = (const float*)d_in[10];
    const float* b0 = (const float*)d_in[11];
    const float* g1 = (const float*)d_in[12];
    const float* b1 = (const float*)d_in[13];
    float* out = (float*)d_out;

    float *X, *Y, *Obuf;
    bf16 *Ah, *Al, *Bh, *Bl, *Wth, *Wtl;
    bf16 *PQh, *PQl, *PKh, *PKl, *PVh, *PVl;
    cudaGetSymbolAddress((void**)&X, g_X);
    cudaGetSymbolAddress((void**)&Y, g_Y);
    cudaGetSymbolAddress((void**)&Obuf, g_O);
    cudaGetSymbolAddress((void**)&Ah, g_Ah);
    cudaGetSymbolAddress((void**)&Al, g_Al);
    cudaGetSymbolAddress((void**)&Bh, g_Bh);
    cudaGetSymbolAddress((void**)&Bl, g_Bl);
    cudaGetSymbolAddress((void**)&PQh, g_PQh);
    cudaGetSymbolAddress((void**)&PQl, g_PQl);
    cudaGetSymbolAddress((void**)&PKh, g_PKh);
    cudaGetSymbolAddress((void**)&PKl, g_PKl);
    cudaGetSymbolAddress((void**)&PVh, g_PVh);
    cudaGetSymbolAddress((void**)&PVl, g_PVl);
    cudaGetSymbolAddress((void**)&Wth, g_Wth);
    cudaGetSymbolAddress((void**)&Wtl, g_Wtl);

    const int GEMM_SMEM = 2 * GSTG;     // 61440
    const int ATTN_SMEM = 2 * 32768;    // 65536
    cudaFuncSetAttribute(proj3_gemm, cudaFuncAttributeMaxDynamicSharedMemorySize, GEMM_SMEM);
    cudaFuncSetAttribute(mlp_gemm, cudaFuncAttributeMaxDynamicSharedMemorySize, GEMM_SMEM);
    cudaFuncSetAttribute(attn_mma, cudaFuncAttributeMaxDynamicSharedMemorySize, ATTN_SMEM);

    conv_wt4<<<dim3(16, 16, 4), dim3(32, 8)>>>(Wq, Wk, Wv, Wo, Wth, Wtl);

    const int CVB = (MROWS * DMODEL / 4) / 256;   // 4096
    conv_act2<<<dim3(CVB, 2), 256>>>(Q, K, Ah, Al, Bh, Bl);

    proj3_gemm<<<dim3(DMODEL / 64, MROWS / 128, 3), 256, GEMM_SMEM>>>(
        Ah, Al, Bh, Bl, Wth, Wtl, bq, bk, bv, PQh, PQl, PKh, PKl, PVh, PVl);

    attn_mma<<<dim3(NQ / 128, NHEAD, BATCH), 256, ATTN_SMEM>>>(
        PQh, PQl, PKh, PKl, PVh, PVl, Obuf);

    ln512<1><<<MROWS, 128>>>(Obuf, g0, b0, X, Ah, Al);

    mlp_gemm<<<dim3(DMODEL / 64, MROWS / 128), 256, GEMM_SMEM>>>(
        Ah, Al, Wth + 3 * (size_t)512 * 512, Wtl + 3 * (size_t)512 * 512, bo, X, Y);

    ln512<0><<<MROWS, 128>>>(Y, g1, b1, out, nullptr, nullptr);
}

// round 6
// speedup vs baseline: 6.6337x; 1.0730x over previous
#include <cuda_runtime.h>
#include <cuda_bf16.h>
#include <cstdint>

#define BATCH 8
#define NQ 1024
#define NK 1024
#define DMODEL 512
#define NHEAD 8
#define DHEAD 64
#define MROWS (BATCH * NQ)   // 8192
#define AST 40               // gemm smem row stride in bf16 (32 data + 8 pad)

typedef __nv_bfloat16 bf16;

// ---------------- scratch (no allocation allowed) ----------------
__device__ float g_X [(size_t)MROWS * DMODEL];   // LN0 output (fp32, resid for MLP)
__device__ float g_Y [(size_t)MROWS * DMODEL];   // MLP output
__device__ float g_O [(size_t)MROWS * DMODEL];   // attention output
__device__ bf16 g_Ah[(size_t)MROWS * DMODEL];
__device__ bf16 g_Al[(size_t)MROWS * DMODEL];
__device__ bf16 g_Bh[(size_t)MROWS * DMODEL];
__device__ bf16 g_Bl[(size_t)MROWS * DMODEL];
__device__ bf16 g_PQh[(size_t)MROWS * DMODEL];
__device__ bf16 g_PQl[(size_t)MROWS * DMODEL];
__device__ bf16 g_PKh[(size_t)MROWS * DMODEL];
__device__ bf16 g_PKl[(size_t)MROWS * DMODEL];
__device__ bf16 g_PVh[(size_t)MROWS * DMODEL];
__device__ bf16 g_PVl[(size_t)MROWS * DMODEL];
__device__ bf16 g_Wth[4 * 512 * 512];   // W^T hi: [n][k]
__device__ bf16 g_Wtl[4 * 512 * 512];   // W^T lo: [n][k]

// ---------------- helpers (base PTX, works on sm_103) ----------------
__device__ __forceinline__ uint32_t s2u(const void* p) {
    uint32_t a;
    asm("{ .reg .u64 t; cvta.to.shared.u64 t, %1; cvt.u32.u64 %0, t; }" : "=r"(a) : "l"(p));
    return a;
}
#define SWZ(o) ((o) ^ (((o) >> 3) & 0x70))

__device__ __forceinline__ void cpa16(uint32_t s, const void* g) {
    asm volatile("cp.async.cg.shared.global [%0], [%1], 16;" :: "r"(s), "l"(g));
}
#define CP_COMMIT() asm volatile("cp.async.commit_group;")
#define CP_WAIT0()  asm volatile("cp.async.wait_group 0;")

__device__ __forceinline__ void ldsm_x4(uint32_t* r, uint32_t addr) {
    asm volatile("ldmatrix.sync.aligned.m8n8.x4.shared.b16 {%0,%1,%2,%3}, [%4];"
                 : "=r"(r[0]), "=r"(r[1]), "=r"(r[2]), "=r"(r[3]) : "r"(addr));
}
__device__ __forceinline__ void ldsm_x4t(uint32_t* r, uint32_t addr) {
    asm volatile("ldmatrix.sync.aligned.m8n8.x4.trans.shared.b16 {%0,%1,%2,%3}, [%4];"
                 : "=r"(r[0]), "=r"(r[1]), "=r"(r[2]), "=r"(r[3]) : "r"(addr));
}
__device__ __forceinline__ void mma16816(float* d, const uint32_t* a, const uint32_t* b) {
    asm volatile(
        "mma.sync.aligned.m16n8k16.row.col.f32.bf16.bf16.f32 "
        "{%0,%1,%2,%3}, {%4,%5,%6,%7}, {%8,%9}, {%0,%1,%2,%3};"
        : "+f"(d[0]), "+f"(d[1]), "+f"(d[2]), "+f"(d[3])
        : "r"(a[0]), "r"(a[1]), "r"(a[2]), "r"(a[3]), "r"(b[0]), "r"(b[1]));
}
__device__ __forceinline__ void split_pack(float x, float y, uint32_t& ph, uint32_t& pl) {
    bf16 hx = __float2bfloat16(x), hy = __float2bfloat16(y);
    __nv_bfloat162 hh(hx, hy);
    ph = *(uint32_t*)&hh;
    __nv_bfloat162 ll(__float2bfloat16(x - __bfloat162float(hx)),
                      __float2bfloat16(y - __bfloat162float(hy)));
    pl = *(uint32_t*)&ll;
}

// ---------------- conversion kernels (merged grids) ----------------
__global__ __launch_bounds__(256) void conv_act2(
    const float* __restrict__ Q, const float* __restrict__ K,
    bf16* __restrict__ Ah, bf16* __restrict__ Al,
    bf16* __restrict__ Bh, bf16* __restrict__ Bl)
{
    const float* X = blockIdx.y ? K : Q;
    bf16* H = blockIdx.y ? Bh : Ah;
    bf16* L = blockIdx.y ? Bl : Al;
    const size_t i = (size_t)blockIdx.x * 256 + threadIdx.x;
    float4 v = ((const float4*)X)[i];
    bf16 h0 = __float2bfloat16(v.x), h1 = __float2bfloat16(v.y);
    bf16 h2 = __float2bfloat16(v.z), h3 = __float2bfloat16(v.w);
    bf16 l0 = __float2bfloat16(v.x - __bfloat162float(h0));
    bf16 l1 = __float2bfloat16(v.y - __bfloat162float(h1));
    bf16 l2 = __float2bfloat16(v.z - __bfloat162float(h2));
    bf16 l3 = __float2bfloat16(v.w - __bfloat162float(h3));
    ((__nv_bfloat162*)H)[2 * i + 0] = __nv_bfloat162(h0, h1);
    ((__nv_bfloat162*)H)[2 * i + 1] = __nv_bfloat162(h2, h3);
    ((__nv_bfloat162*)L)[2 * i + 0] = __nv_bfloat162(l0, l1);
    ((__nv_bfloat162*)L)[2 * i + 1] = __nv_bfloat162(l2, l3);
}

__global__ __launch_bounds__(256) void conv_wt4(
    const float* __restrict__ W0, const float* __restrict__ W1,
    const float* __restrict__ W2, const float* __restrict__ W3,
    bf16* __restrict__ Th, bf16* __restrict__ Tl)
{
    const int z = blockIdx.z;
    const float* W = (z == 0) ? W0 : (z == 1) ? W1 : (z == 2) ? W2 : W3;
    bf16* ThZ = Th + (size_t)z * 512 * 512;
    bf16* TlZ = Tl + (size_t)z * 512 * 512;
    __shared__ float t[32][33];
    const int bx = blockIdx.x * 32;  // n
    const int by = blockIdx.y * 32;  // k
    const int x = threadIdx.x, y0 = threadIdx.y;
    #pragma unroll
    for (int j = 0; j < 32; j += 8)
        t[y0 + j][x] = W[(size_t)(by + y0 + j) * 512 + bx + x];
    __syncthreads();
    #pragma unroll
    for (int j = 0; j < 32; j += 8) {
        float v = t[x][y0 + j];
        bf16 h = __float2bfloat16(v);
        bf16 l = __float2bfloat16(v - __bfloat162float(h));
        const size_t o = (size_t)(bx + y0 + j) * 512 + by + x;
        ThZ[o] = h;
        TlZ[o] = l;
    }
}

// ---------------- GEMM core (cp.async double-buffered) ----------------
#define GSTG 30720
__device__ __forceinline__ void gemm_core(
    const bf16* __restrict__ Ah, const bf16* __restrict__ Al,
    const bf16* __restrict__ Bh, const bf16* __restrict__ Bl,
    const float* __restrict__ bias, const float* __restrict__ resid,
    float* __restrict__ C, bf16* __restrict__ Chi, bf16* __restrict__ Clo,
    int fuse, char* smem, int m0, int n0)
{
    const int tid = threadIdx.x, wid = tid >> 5, lane = tid & 31;
    const int warp_m = (wid & 3) * 32, warp_n = (wid >> 2) * 32;
    const uint32_t sb = s2u(smem);

    float acc[2][4][4];
    #pragma unroll
    for (int mt = 0; mt < 2; mt++)
        #pragma unroll
        for (int nt = 0; nt < 4; nt++)
            #pragma unroll
            for (int i = 0; i < 4; i++) acc[mt][nt][i] = 0.f;

    const int la_row0 = tid >> 2, la_c = tid & 3;
    const int lb_row = tid >> 2, lb_c = tid & 3;

    auto issue = [&](int kc, int stg) {
        const uint32_t base = sb + stg * GSTG;
        #pragma unroll
        for (int i = 0; i < 2; i++) {
            const int row = la_row0 + i * 64;
            const size_t go = (size_t)(m0 + row) * 512 + kc * 32 + la_c * 8;
            const uint32_t so = row * (AST * 2) + la_c * 16;
            cpa16(base + so, Ah + go);
            cpa16(base + 10240 + so, Al + go);
        }
        {
            const size_t go = (size_t)(n0 + lb_row) * 512 + kc * 32 + lb_c * 8;
            const uint32_t so = lb_row * (AST * 2) + lb_c * 16;
            cpa16(base + 20480 + so, Bh + go);
            cpa16(base + 25600 + so, Bl + go);
        }
        CP_COMMIT();
    };

    issue(0, 0);
    CP_WAIT0();
    __syncthreads();

    const int a_row = lane & 15, a_cb = (lane >> 4) * 8;
    const int b_nof = (lane & 7) + ((lane >> 4) & 1) * 8;
    const int b_kof = ((lane >> 3) & 1) * 8;

    for (int kc = 0; kc < 16; kc++) {
        const int cur = kc & 1;
        if (kc < 15) issue(kc + 1, cur ^ 1);
        const uint32_t base = sb + cur * GSTG;

        #pragma unroll
        for (int ks = 0; ks < 2; ks++) {
            const int k16 = ks * 16;
            uint32_t afh[2][4], afl[2][4], bfh[2][4], bfl[2][4];
            #pragma unroll
            for (int mt = 0; mt < 2; mt++) {
                const uint32_t off = (warp_m + mt * 16 + a_row) * (AST * 2) + (k16 + a_cb) * 2;
                ldsm_x4(afh[mt], base + off);
                ldsm_x4(afl[mt], base + 10240 + off);
            }
            #pragma unroll
            for (int nb = 0; nb < 2; nb++) {
                const uint32_t off = (warp_n + nb * 16 + b_nof) * (AST * 2) + (k16 + b_kof) * 2;
                ldsm_x4(bfh[nb], base + 20480 + off);
                ldsm_x4(bfl[nb], base + 25600 + off);
            }
            #pragma unroll
            for (int mt = 0; mt < 2; mt++)
                #pragma unroll
                for (int nt = 0; nt < 4; nt++) {
                    const uint32_t* bh = &bfh[nt >> 1][(nt & 1) * 2];
                    const uint32_t* bl = &bfl[nt >> 1][(nt & 1) * 2];
                    mma16816(acc[mt][nt], afh[mt], bh);
                    mma16816(acc[mt][nt], afh[mt], bl);
                    mma16816(acc[mt][nt], afl[mt], bh);
                }
        }
        CP_WAIT0();
        __syncthreads();
    }

    const int r0 = lane >> 2, c0 = (lane & 3) * 2;
    #pragma unroll
    for (int mt = 0; mt < 2; mt++) {
        #pragma unroll
        for (int nt = 0; nt < 4; nt++) {
            const int cc = n0 + warp_n + nt * 8 + c0;
            const float2 bb = *(const float2*)(bias + cc);
            #pragma unroll
            for (int half = 0; half < 2; half++) {
                const int rr = m0 + warp_m + mt * 16 + r0 + half * 8;
                float ox = acc[mt][nt][half * 2 + 0] + bb.x;
                float oy = acc[mt][nt][half * 2 + 1] + bb.y;
                const size_t go = (size_t)rr * 512 + cc;
                if (Chi) {
                    uint32_t ph, pl;
                    split_pack(ox, oy, ph, pl);
                    *(uint32_t*)(Chi + go) = ph;
                    *(uint32_t*)(Clo + go) = pl;
                } else {
                    if (fuse) {
                        float2 xr = *(const float2*)(resid + go);
                        ox = xr.x + fmaxf(ox, 0.f);
                        oy = xr.y + fmaxf(oy, 0.f);
                    }
                    *(float2*)(C + go) = make_float2(ox, oy);
                }
            }
        }
    }
}

__global__ __launch_bounds__(256, 2) void proj3_gemm(
    const bf16* __restrict__ QAh, const bf16* __restrict__ QAl,
    const bf16* __restrict__ KAh, const bf16* __restrict__ KAl,
    const bf16* __restrict__ Wth, const bf16* __restrict__ Wtl,
    const float* __restrict__ bq, const float* __restrict__ bk,
    const float* __restrict__ bv,
    bf16* __restrict__ PQh, bf16* __restrict__ PQl,
    bf16* __restrict__ PKh, bf16* __restrict__ PKl,
    bf16* __restrict__ PVh, bf16* __restrict__ PVl)
{
    extern __shared__ char smem[];
    const int z = blockIdx.z;
    const bf16* Ah = (z == 0) ? QAh : KAh;
    const bf16* Al = (z == 0) ? QAl : KAl;
    const bf16* Bh = Wth + (size_t)z * 512 * 512;
    const bf16* Bl = Wtl + (size_t)z * 512 * 512;
    const float* bias = (z == 0) ? bq : (z == 1) ? bk : bv;
    bf16* Chi = (z == 0) ? PQh : (z == 1) ? PKh : PVh;
    bf16* Clo = (z == 0) ? PQl : (z == 1) ? PKl : PVl;
    gemm_core(Ah, Al, Bh, Bl, bias, nullptr, nullptr, Chi, Clo, 0, smem,
              blockIdx.y * 128, blockIdx.x * 64);
}

__global__ __launch_bounds__(256, 2) void mlp_gemm(
    const bf16* __restrict__ Ah, const bf16* __restrict__ Al,
    const bf16* __restrict__ Bh, const bf16* __restrict__ Bl,
    const float* __restrict__ bias, const float* __restrict__ resid,
    float* __restrict__ C)
{
    extern __shared__ char smem[];
    gemm_core(Ah, Al, Bh, Bl, bias, resid, C, nullptr, nullptr, 1, smem,
              blockIdx.y * 128, blockIdx.x * 64);
}

// ---------------- attention: mma flash kernel (cp.async pipelined, 2 CTA/SM) ----------------
__global__ __launch_bounds__(256, 2) void attn_mma(
    const bf16* __restrict__ Qh, const bf16* __restrict__ Ql,
    const bf16* __restrict__ Kh, const bf16* __restrict__ Kl,
    const bf16* __restrict__ Vh, const bf16* __restrict__ Vl,
    float* __restrict__ O)
{
    extern __shared__ __align__(1024) char sm[];
    const uint32_t sb = s2u(sm);

    const int qt = blockIdx.x, h = blockIdx.y, b = blockIdx.z;
    const int tid = threadIdx.x, wid = tid >> 5, lane = tid & 31;
    const int hcol = h * DHEAD;
    const size_t qbase = (size_t)(b * NQ + qt * 128);

    // ---- stage Q tile (128 x 64) hi -> sm[0:16K], lo -> sm[16K:32K]
    for (int i = tid; i < 1024; i += 256) {
        const int row = i >> 3, u = i & 7;
        const size_t g = (qbase + row) * 512 + hcol + u * 8;
        const int off = SWZ(row * 128 + u * 16);
        *(uint4*)(sm + off)         = *(const uint4*)(Qh + g);
        *(uint4*)(sm + 16384 + off) = *(const uint4*)(Ql + g);
    }
    __syncthreads();

    uint32_t qfh[4][4], qfl[4][4];
    {
        const int qrow = wid * 16 + (lane & 15);
        #pragma unroll
        for (int t = 0; t < 4; t++) {
            const int off = SWZ(qrow * 128 + (t * 16 + (lane >> 4) * 8) * 2);
            ldsm_x4(qfh[t], sb + off);
            ldsm_x4(qfl[t], sb + 16384 + off);
        }
    }
    __syncthreads();

    const int l_row = tid >> 3, l_u = tid & 7;
    auto issue = [&](int kt, int stg) {
        const uint32_t base = sb + stg * 32768;
        #pragma unroll
        for (int i = 0; i < 2; i++) {
            const int row = l_row + i * 32;
            const size_t g = ((size_t)(b * NK + kt * 64 + row)) * 512 + hcol + l_u * 8;
            const uint32_t off = SWZ(row * 128 + l_u * 16);
            cpa16(base + off, Kh + g);
            cpa16(base + 8192 + off, Kl + g);
            cpa16(base + 16384 + off, Vh + g);
            cpa16(base + 24576 + off, Vl + g);
        }
        CP_COMMIT();
    };

    float m0 = -1e30f, m1 = -1e30f, l0 = 0.f, l1 = 0.f;
    float o[8][4];
    #pragma unroll
    for (int i = 0; i < 8; i++)
        #pragma unroll
        for (int j = 0; j < 4; j++) o[i][j] = 0.f;

    issue(0, 0);
    CP_WAIT0();
    __syncthreads();

    for (int kt = 0; kt < 16; kt++) {
        const int cur = kt & 1;
        if (kt < 15) issue(kt + 1, cur ^ 1);
        const uint32_t base = sb + cur * 32768;

        float s[8][4];
        #pragma unroll
        for (int i = 0; i < 8; i++)
            #pragma unroll
            for (int j = 0; j < 4; j++) s[i][j] = 0.f;

        #pragma unroll
        for (int nb = 0; nb < 4; nb++) {
            #pragma unroll
            for (int t = 0; t < 4; t++) {
                uint32_t bh[4], bl[4];
                const int krow = nb * 16 + (lane & 7) + ((lane >> 4) & 1) * 8;
                const uint32_t off = SWZ(krow * 128 + (t * 16 + ((lane >> 3) & 1) * 8) * 2);
                ldsm_x4(bh, base + off);
                ldsm_x4(bl, base + 8192 + off);
                mma16816(s[2 * nb], qfh[t], bh);
                mma16816(s[2 * nb], qfh[t], bl);
                mma16816(s[2 * nb], qfl[t], bh);
                mma16816(s[2 * nb + 1], qfh[t], bh + 2);
                mma16816(s[2 * nb + 1], qfh[t], bl + 2);
                mma16816(s[2 * nb + 1], qfl[t], bh + 2);
            }
        }

        float tm0 = -1e30f, tm1 = -1e30f;
        #pragma unroll
        for (int nt = 0; nt < 8; nt++) {
            #pragma unroll
            for (int j = 0; j < 4; j++) s[nt][j] *= 0.125f;
            tm0 = fmaxf(tm0, fmaxf(s[nt][0], s[nt][1]));
            tm1 = fmaxf(tm1, fmaxf(s[nt][2], s[nt][3]));
        }
        tm0 = fmaxf(tm0, __shfl_xor_sync(0xffffffffu, tm0, 1));
        tm0 = fmaxf(tm0, __shfl_xor_sync(0xffffffffu, tm0, 2));
        tm1 = fmaxf(tm1, __shfl_xor_sync(0xffffffffu, tm1, 1));
        tm1 = fmaxf(tm1, __shfl_xor_sync(0xffffffffu, tm1, 2));

        const float mn0 = fmaxf(m0, tm0), mn1 = fmaxf(m1, tm1);
        const float cr0 = __expf(m0 - mn0), cr1 = __expf(m1 - mn1);
        m0 = mn0; m1 = mn1;
        #pragma unroll
        for (int i = 0; i < 8; i++) {
            o[i][0] *= cr0; o[i][1] *= cr0;
            o[i][2] *= cr1; o[i][3] *= cr1;
        }
        float rs0 = 0.f, rs1 = 0.f;
        #pragma unroll
        for (int nt = 0; nt < 8; nt++) {
            s[nt][0] = __expf(s[nt][0] - mn0);
            s[nt][1] = __expf(s[nt][1] - mn0);
            s[nt][2] = __expf(s[nt][2] - mn1);
            s[nt][3] = __expf(s[nt][3] - mn1);
            rs0 += s[nt][0] + s[nt][1];
            rs1 += s[nt][2] + s[nt][3];
        }
        rs0 += __shfl_xor_sync(0xffffffffu, rs0, 1);
        rs0 += __shfl_xor_sync(0xffffffffu, rs0, 2);
        rs1 += __shfl_xor_sync(0xffffffffu, rs1, 1);
        rs1 += __shfl_xor_sync(0xffffffffu, rs1, 2);
        l0 = l0 * cr0 + rs0;
        l1 = l1 * cr1 + rs1;

        #pragma unroll
        for (int j = 0; j < 4; j++) {
            uint32_t ah[4], al[4];
            split_pack(s[2 * j][0], s[2 * j][1], ah[0], al[0]);
            split_pack(s[2 * j][2], s[2 * j][3], ah[1], al[1]);
            split_pack(s[2 * j + 1][0], s[2 * j + 1][1], ah[2], al[2]);
            split_pack(s[2 * j + 1][2], s[2 * j + 1][3], ah[3], al[3]);
            const int vrow = j * 16 + (lane & 15);
            #pragma unroll
            for (int nb = 0; nb < 4; nb++) {
                uint32_t vh[4], vl[4];
                const uint32_t off = SWZ(vrow * 128 + (nb * 16 + (lane >> 4) * 8) * 2);
                ldsm_x4t(vh, base + 16384 + off);
                ldsm_x4t(vl, base + 24576 + off);
                mma16816(o[2 * nb], ah, vh);
                mma16816(o[2 * nb], al, vh);
                mma16816(o[2 * nb], ah, vl);
                mma16816(o[2 * nb + 1], ah, vh + 2);
                mma16816(o[2 * nb + 1], al, vh + 2);
                mma16816(o[2 * nb + 1], ah, vl + 2);
            }
        }
        CP_WAIT0();
        __syncthreads();
    }

    const float inv0 = 1.f / l0, inv1 = 1.f / l1;
    const int row0 = wid * 16 + (lane >> 2);
    #pragma unroll
    for (int nt = 0; nt < 8; nt++) {
        const int col = hcol + nt * 8 + (lane & 3) * 2;
        #pragma unroll
        for (int half = 0; half < 2; half++) {
            const size_t g = (qbase + row0 + half * 8) * 512 + col;
            __nv_bfloat162 qh2 = *(const __nv_bfloat162*)(Qh + g);
            __nv_bfloat162 ql2 = *(const __nv_bfloat162*)(Ql + g);
            const float inv = half ? inv1 : inv0;
            float2 out;
            out.x = o[nt][half * 2 + 0] * inv + __bfloat162float(qh2.x) + __bfloat162float(ql2.x);
            out.y = o[nt][half * 2 + 1] * inv + __bfloat162float(qh2.y) + __bfloat162float(ql2.y);
            *(float2*)(O + g) = out;
        }
    }
}

// ---------------- LayerNorm (optionally with bf16 hi/lo split output) ----------------
template <int SPLIT>
__global__ __launch_bounds__(128) void ln512(
    const float* __restrict__ X, const float* __restrict__ g,
    const float* __restrict__ be, float* __restrict__ Y,
    bf16* __restrict__ H, bf16* __restrict__ L)
{
    const int row = blockIdx.x;
    const int tid = threadIdx.x;
    const float* x = X + (size_t)row * 512;

    float4 v = *(const float4*)(x + tid * 4);
    float s  = v.x + v.y + v.z + v.w;
    float ss = v.x * v.x + v.y * v.y + v.z * v.z + v.w * v.w;
    #pragma unroll
    for (int o = 16; o; o >>= 1) {
        s  += __shfl_xor_sync(0xffffffffu, s, o);
        ss += __shfl_xor_sync(0xffffffffu, ss, o);
    }
    __shared__ float sm[4], sm2[4];
    if ((tid & 31) == 0) { sm[tid >> 5] = s; sm2[tid >> 5] = ss; }
    __syncthreads();
    const float ts  = sm[0] + sm[1] + sm[2] + sm[3];
    const float tss = sm2[0] + sm2[1] + sm2[2] + sm2[3];
    const float mean = ts * (1.f / 512.f);
    const float var  = tss * (1.f / 512.f) - mean * mean;
    const float rstd = rsqrtf(var + 1e-5f);

    float4 gg = *(const float4*)(g + tid * 4);
    float4 bb = *(const float4*)(be + tid * 4);
    float4 o;
    o.x = (v.x - mean) * rstd * gg.x + bb.x;
    o.y = (v.y - mean) * rstd * gg.y + bb.y;
    o.z = (v.z - mean) * rstd * gg.z + bb.z;
    o.w = (v.w - mean) * rstd * gg.w + bb.w;
    *(float4*)(Y + (size_t)row * 512 + tid * 4) = o;
    if (SPLIT) {
        uint32_t ph0, pl0, ph1, pl1;
        split_pack(o.x, o.y, ph0, pl0);
        split_pack(o.z, o.w, ph1, pl1);
        const size_t go = (size_t)row * 512 + tid * 4;
        *(uint32_t*)(H + go)     = ph0;
        *(uint32_t*)(H + go + 2) = ph1;
        *(uint32_t*)(L + go)     = pl0;
        *(uint32_t*)(L + go + 2) = pl1;
    }
}

// ---------------- launch ----------------
extern "C" void kernel_launch(void* const* d_in, const int* in_sizes, int n_in,
                              void* d_out, int out_size)
{
    const float* Q  = (const float*)d_in[0];
    const float* K  = (const float*)d_in[1];
    const float* Wq = (const float*)d_in[2];
    const float* bq = (const float*)d_in[3];
    const float* Wk = (const float*)d_in[4];
    const float* bk = (const float*)d_in[5];
    const float* Wv = (const float*)d_in[6];
    const float* bv = (const float*)d_in[7];
    const float* Wo = (const float*)d_in[8];
    const float* bo = (const float*)d_in[9];
    const float* g0 = (const float*)d_in[10];
    const float* b0 = (const float*)d_in[11];
    const float* g1 = (const float*)d_in[12];
    const float* b1 = (const float*)d_in[13];
    float* out = (float*)d_out;

    float *X, *Y, *Obuf;
    bf16 *Ah, *Al, *Bh, *Bl, *Wth, *Wtl;
    bf16 *PQh, *PQl, *PKh, *PKl, *PVh, *PVl;
    cudaGetSymbolAddress((void**)&X, g_X);
    cudaGetSymbolAddress((void**)&Y, g_Y);
    cudaGetSymbolAddress((void**)&Obuf, g_O);
    cudaGetSymbolAddress((void**)&Ah, g_Ah);
    cudaGetSymbolAddress((void**)&Al, g_Al);
    cudaGetSymbolAddress((void**)&Bh, g_Bh);
    cudaGetSymbolAddress((void**)&Bl, g_Bl);
    cudaGetSymbolAddress((void**)&PQh, g_PQh);
    cudaGetSymbolAddress((void**)&PQl, g_PQl);
    cudaGetSymbolAddress((void**)&PKh, g_PKh);
    cudaGetSymbolAddress((void**)&PKl, g_PKl);
    cudaGetSymbolAddress((void**)&PVh, g_PVh);
    cudaGetSymbolAddress((void**)&PVl, g_PVl);
    cudaGetSymbolAddress((void**)&Wth, g_Wth);
    cudaGetSymbolAddress((void**)&Wtl, g_Wtl);

    const int GEMM_SMEM = 2 * GSTG;     // 61440
    const int ATTN_SMEM = 2 * 32768;    // 65536
    cudaFuncSetAttribute(proj3_gemm, cudaFuncAttributeMaxDynamicSharedMemorySize, GEMM_SMEM);
    cudaFuncSetAttribute(mlp_gemm, cudaFuncAttributeMaxDynamicSharedMemorySize, GEMM_SMEM);
    cudaFuncSetAttribute(attn_mma, cudaFuncAttributeMaxDynamicSharedMemorySize, ATTN_SMEM);

    conv_wt4<<<dim3(16, 16, 4), dim3(32, 8)>>>(Wq, Wk, Wv, Wo, Wth, Wtl);

    const int CVB = (MROWS * DMODEL / 4) / 256;   // 4096
    conv_act2<<<dim3(CVB, 2), 256>>>(Q, K, Ah, Al, Bh, Bl);

    proj3_gemm<<<dim3(DMODEL / 64, MROWS / 128, 3), 256, GEMM_SMEM>>>(
        Ah, Al, Bh, Bl, Wth, Wtl, bq, bk, bv, PQh, PQl, PKh, PKl, PVh, PVl);

    attn_mma<<<dim3(NQ / 128, NHEAD, BATCH), 256, ATTN_SMEM>>>(
        PQh, PQl, PKh, PKl, PVh, PVl, Obuf);

    ln512<1><<<MROWS, 128>>>(Obuf, g0, b0, X, Ah, Al);

    mlp_gemm<<<dim3(DMODEL / 64, MROWS / 128), 256, GEMM_SMEM>>>(
        Ah, Al, Wth + 3 * (size_t)512 * 512, Wtl + 3 * (size_t)512 * 512, bo, X, Y);

    ln512<0><<<MROWS, 128>>>(Y, g1, b1, out, nullptr, nullptr);
}